// round 14
// baseline (speedup 1.0000x reference)
#include <cuda_runtime.h>
#include <cstddef>
#include <cstdint>

// ---------------------------------------------------------------------------
// DA-RNN: B=512, T=64, I=128, H=128, E=127
// Round 12: same theory as R11 (L2 evict_last on re-read streams), corrected
// PTX encoding: createpolicy + ld.global.nc.L2::cache_hint (scalar-legal).
// ---------------------------------------------------------------------------

#define B_  512
#define T_  64
#define I_  128
#define H_  128
#define E_  127
#define SN  (B_*H_)   // 65536

// ------------------------- device scratch (static) -------------------------
__device__ float g_state[8 * SN];
__device__ float g_P[(size_t)B_ * E_ * T_];      // enc pre-proj (b,e,j)
__device__ float g_P2[(size_t)B_ * 64 * 128];    // enc pre-proj (b,j,e)
__device__ float g_hexp[(size_t)B_ * T_ * H_];   // (b,t,h)
__device__ float g_Hproj2[(size_t)B_ * 128 * 64];// dec pre-proj (b,j,t)
__device__ float g_W1Te[320 * 64];
__device__ float g_W1Td[384 * 128];
__device__ float g_xs[B_ * E_];
__device__ float g_din[B_];
__device__ float g_partial[B_ * H_];

// ------------------------------ math helpers -------------------------------
__device__ __forceinline__ float rcp_fast(float q) {
    float r = __uint_as_float(0x7EF311C3u - __float_as_uint(q));
    r = r * fmaf(-q, r, 2.0f);
    r = r * fmaf(-q, r, 2.0f);
    r = r * fmaf(-q, r, 2.0f);
    return r;
}
__device__ __forceinline__ float tanh_fma(float x) {
    const float kClamp = 7.90531110763549805f;
    x = fminf(fmaxf(x, -kClamp), kClamp);
    float x2 = x * x;
    float p = -2.76076847742355e-16f;
    p = fmaf(p, x2, 2.00018790482477e-13f);
    p = fmaf(p, x2, -8.60467152213735e-11f);
    p = fmaf(p, x2, 5.12229709037114e-08f);
    p = fmaf(p, x2, 1.48572235717979e-05f);
    p = fmaf(p, x2, 6.37261928875436e-04f);
    p = fmaf(p, x2, 4.89352455891786e-03f);
    p = x * p;
    float q = 1.19825839466702e-06f;
    q = fmaf(q, x2, 1.18534705686654e-04f);
    q = fmaf(q, x2, 2.26843463243900e-03f);
    q = fmaf(q, x2, 4.89352518554385e-03f);
    return p * rcp_fast(q);
}
__device__ __forceinline__ float sig_fma(float x) {
    return fmaf(tanh_fma(0.5f * x), 0.5f, 0.5f);
}
// L2 evict_last read via cache-hint policy (scalar-legal encoding)
__device__ __forceinline__ float ldg_last(const float* p) {
    float v;
    asm("{\n\t"
        ".reg .b64 pol;\n\t"
        "createpolicy.fractional.L2::evict_last.b64 pol, 1.0;\n\t"
        "ld.global.nc.L2::cache_hint.f32 %0, [%1], pol;\n\t"
        "}" : "=f"(v) : "l"(p));
    return v;
}

// ------------------------- prep: W transposes + zero -----------------------
__global__ void darnn_prep(const float* __restrict__ aW1, const float* __restrict__ adW1,
                           float* __restrict__ W1Te, float* __restrict__ W1Td,
                           float* h0, float* c0, float* h1, float* c1) {
    int i = blockIdx.x * blockDim.x + threadIdx.x;
    if (i < 64 * 320) { int r = i / 320, c = i % 320; W1Te[c * 64 + r] = aW1[i]; }
    if (i < 128 * 384) { int r = i / 384, c = i % 384; W1Td[c * 128 + r] = adW1[i]; }
    if (i < SN) { h0[i] = 0.f; c0[i] = 0.f; h1[i] = 0.f; c1[i] = 0.f; }
}

__global__ void darnn_zero_states(float* h0, float* c0, float* h1, float* c1) {
    int i = blockIdx.x * blockDim.x + threadIdx.x;
    if (i < SN) { h0[i] = 0.f; c0[i] = 0.f; h1[i] = 0.f; c1[i] = 0.f; }
}

// ------------------ encoder attention pre-projection (once) ----------------
__global__ void darnn_penc(const float* __restrict__ input,
                           const float* __restrict__ W1T,
                           const float* __restrict__ b1,
                           float* __restrict__ P) {
    int row0 = blockIdx.x * 4;
    int tx = threadIdx.x;
    int j = tx & 63;
    int r = tx >> 6;
    int row = row0 + r;
    int b = row / E_;
    int e = row % E_;
    __shared__ float xsm[4][65];
    xsm[r][j] = input[((size_t)b * T_ + j) * I_ + 1 + e];
    __syncthreads();
    float acc = b1[j];
#pragma unroll 8
    for (int k = 0; k < 64; k++)
        acc += xsm[r][k] * W1T[(256 + k) * 64 + j];
    P[(size_t)row * 64 + j] = acc;
}

// -------- transpose P (b,e,j) -> P2 (b,j,e) --------------------------------
__global__ void darnn_ptrans(const float* __restrict__ P, float* __restrict__ P2) {
    int bb = blockIdx.x >> 1;
    int j0 = (blockIdx.x & 1) * 32;
    __shared__ float sm[128][33];
    int tx = threadIdx.x;
    int j = tx & 31, e0 = tx >> 5;
#pragma unroll
    for (int i = 0; i < 16; i++) {
        int e = e0 + 8 * i;
        sm[e][j] = (e < E_) ? P[((size_t)bb * E_ + e) * 64 + j0 + j] : 0.f;
    }
    __syncthreads();
    int e = tx & 127, jg = tx >> 7;
#pragma unroll
    for (int p = 0; p < 16; p++) {
        int jj = jg + 2 * p;
        P2[((size_t)bb * 64 + j0 + jj) * 128 + e] = sm[e][jj];
    }
}

// ------ decoder attention pre-projection (once), writes (b,j,t) layout -----
__global__ void darnn_hproj(const float* __restrict__ hexp,
                            const float* __restrict__ W1dT,
                            const float* __restrict__ b1d,
                            float* __restrict__ Hproj2) {
    int row0 = blockIdx.x * 16;
    int b = row0 >> 6, t0 = row0 & 63;
    int tx = threadIdx.x;
    int j = tx & 127;
    int rs = tx >> 7;
    __shared__ float hs[16][129];
    __shared__ float outs[16][133];
#pragma unroll
    for (int i = 0; i < 8; i++) {
        int r = rs + 2 * i;
        hs[r][j] = hexp[((size_t)row0 + r) * H_ + j];
    }
    __syncthreads();
    float acc[8];
#pragma unroll
    for (int i = 0; i < 8; i++) acc[i] = b1d[j];
    for (int k = 0; k < 128; k++) {
        float w = W1dT[(256 + k) * 128 + j];
#pragma unroll
        for (int i = 0; i < 8; i++) acc[i] += hs[rs + 2 * i][k] * w;
    }
#pragma unroll
    for (int i = 0; i < 8; i++) outs[rs + 2 * i][j] = acc[i];
    __syncthreads();
    int t = tx & 15, jp = tx >> 4;
#pragma unroll
    for (int p = 0; p < 8; p++) {
        int jj = jp + 16 * p;
        Hproj2[((size_t)b * 128 + jj) * 64 + t0 + t] = outs[t][jj];
    }
}

// --------------------- encoder attention step (512 thr) ---------------------
__global__ __launch_bounds__(512)
void darnn_enc_attn(const float* __restrict__ input,
                    const float* __restrict__ h1, const float* __restrict__ c1,
                    const float* __restrict__ W1T,
                    const float* __restrict__ W2,
                    const float* __restrict__ b2,
                    const float* __restrict__ P2,
                    float* __restrict__ xs, int t) {
    int b = blockIdx.x;
    int tx = threadIdx.x;
    __shared__ float h1s[128], c1s[128], W2s[64], hvJ[64];
    __shared__ float hpart[8][64];
    __shared__ float part[4][128];
    __shared__ float lgs[128], red[128];
    if (tx < 128) { h1s[tx] = h1[b * H_ + tx]; c1s[tx] = c1[b * H_ + tx]; }
    else if (tx < 192) W2s[tx - 128] = W2[tx - 128];
    __syncthreads();
    {
        int j = tx & 63, pg = tx >> 6;
        int hlo = pg * 16;
        float a = 0.f;
#pragma unroll
        for (int i = 0; i < 16; i++) {
            int h = hlo + i;
            a += h1s[h] * W1T[h * 64 + j] + c1s[h] * W1T[(128 + h) * 64 + j];
        }
        hpart[pg][j] = a;
    }
    __syncthreads();
    if (tx < 64) {
        float a = 0.f;
#pragma unroll
        for (int p = 0; p < 8; p++) a += hpart[p][tx];
        hvJ[tx] = a;
    }
    __syncthreads();
    {
        int e = tx & 127, q = tx >> 7;
        const float* Pr = P2 + (size_t)b * 64 * 128 + e;
        float acc = (q == 0) ? b2[0] : 0.f;
#pragma unroll
        for (int jj = 0; jj < 16; jj++) {
            int j = q * 16 + jj;
            acc += tanh_fma(ldg_last(Pr + j * 128) + hvJ[j]) * W2s[j];
        }
        part[q][e] = acc;
    }
    __syncthreads();
    if (tx < 128) {
        float lg = part[0][tx] + part[1][tx] + part[2][tx] + part[3][tx];
        if (tx >= E_) lg = -3.0e38f;
        lgs[tx] = lg;
        red[tx] = lg;
    }
    __syncthreads();
    for (int s = 64; s > 0; s >>= 1) { if (tx < s) red[tx] = fmaxf(red[tx], red[tx + s]); __syncthreads(); }
    float m = red[0];
    __syncthreads();
    float ex = 0.f;
    if (tx < 128) {
        ex = (tx < E_) ? __expf(lgs[tx] - m) : 0.f;
        red[tx] = ex;
    }
    __syncthreads();
    for (int s = 64; s > 0; s >>= 1) { if (tx < s) red[tx] += red[tx + s]; __syncthreads(); }
    float inv = 1.0f / red[0];
    if (tx < E_)
        xs[b * E_ + tx] = input[((size_t)b * T_ + t) * I_ + 1 + tx] * ex * inv;
}

// --------------------- decoder attention step (512 thr) ---------------------
__global__ __launch_bounds__(512)
void darnn_dec_attn(const float* __restrict__ input,
                    const float* __restrict__ h1, const float* __restrict__ c1,
                    const float* __restrict__ W1dT,
                    const float* __restrict__ W2d,
                    const float* __restrict__ b2d,
                    const float* __restrict__ Hproj2,
                    const float* __restrict__ hexp,
                    const float* __restrict__ decinW,
                    const float* __restrict__ decinB,
                    float* __restrict__ din,
                    float* __restrict__ partial, int t) {
    int b = blockIdx.x;
    int tx = threadIdx.x;
    __shared__ float h1s[128], c1s[128], W2s[128], hvJ[128];
    __shared__ float hpart[4][128];
    __shared__ float part2[8][64];
    __shared__ float cpart[4][128];
    __shared__ float a_s[64], lgs[64], red[128];
    if (tx < 128) { h1s[tx] = h1[b * H_ + tx]; c1s[tx] = c1[b * H_ + tx]; }
    else if (tx < 256) W2s[tx - 128] = W2d[tx - 128];
    __syncthreads();
    {
        int j = tx & 127, pg = tx >> 7;
        int hlo = pg * 32;
        float a = 0.f;
#pragma unroll
        for (int i = 0; i < 32; i++) {
            int h = hlo + i;
            a += h1s[h] * W1dT[h * 128 + j] + c1s[h] * W1dT[(128 + h) * 128 + j];
        }
        hpart[pg][j] = a;
    }
    __syncthreads();
    if (tx < 128)
        hvJ[tx] = hpart[0][tx] + hpart[1][tx] + hpart[2][tx] + hpart[3][tx];
    __syncthreads();
    {
        int tt = tx & 63, oc = tx >> 6;
        const float* Pr = Hproj2 + (size_t)b * 128 * 64 + tt;
        float acc = (oc == 0) ? b2d[0] : 0.f;
#pragma unroll
        for (int jj = 0; jj < 16; jj++) {
            int j = oc * 16 + jj;
            acc += tanh_fma(ldg_last(Pr + j * 64) + hvJ[j]) * W2s[j];
        }
        part2[oc][tt] = acc;
    }
    __syncthreads();
    if (tx < 64) {
        float lg = 0.f;
#pragma unroll
        for (int p = 0; p < 8; p++) lg += part2[p][tx];
        lgs[tx] = lg;
        red[tx] = lg;
    }
    __syncthreads();
    for (int s = 32; s > 0; s >>= 1) { if (tx < s) red[tx] = fmaxf(red[tx], red[tx + s]); __syncthreads(); }
    float m = red[0];
    __syncthreads();
    if (tx < 64) red[tx] = __expf(lgs[tx] - m);
    __syncthreads();
    float ex = (tx < 64) ? red[tx] : 0.f;
    for (int s = 32; s > 0; s >>= 1) { if (tx < s) red[tx] += red[tx + s]; __syncthreads(); }
    if (tx < 64) a_s[tx] = ex / red[0];
    __syncthreads();
    {
        int h = tx & 127, tg = tx >> 7;
        float p = 0.f;
#pragma unroll
        for (int i = 0; i < 16; i++) {
            int tt = tg * 16 + i;
            p += a_s[tt] * ldg_last(hexp + ((size_t)b * T_ + tt) * H_ + h);
        }
        cpart[tg][h] = p;
    }
    __syncthreads();
    if (tx < 128) {
        float p = cpart[0][tx] + cpart[1][tx] + cpart[2][tx] + cpart[3][tx];
        partial[b * H_ + tx] = p;
        red[tx] = p * decinW[tx];
    }
    __syncthreads();
    for (int s = 64; s > 0; s >>= 1) { if (tx < s) red[tx] += red[tx + s]; __syncthreads(); }
    if (tx == 0)
        din[b] = red[0] + decinW[128] * input[((size_t)b * T_ + t) * I_ + 0] + decinB[0];
}

// ------------------------------ fused LSTM cell -----------------------------
__global__ void darnn_lstm_cell(const float* __restrict__ X, int Kx,
                                const float* __restrict__ Wih,
                                const float* __restrict__ Hp,
                                const float* __restrict__ Whh,
                                const float* __restrict__ bih,
                                const float* __restrict__ bhh,
                                const float* __restrict__ Cp,
                                float* __restrict__ Hout,
                                float* __restrict__ Cout,
                                float* __restrict__ Hcopy, int hstride) {
    const int b0 = blockIdx.x * 16;
    const int h0 = blockIdx.y * 32;
    const int tx = threadIdx.x;
    const int bq = tx & 3;
    const int hl = tx >> 2;
    const int lane = tx & 31;
    const int wr = tx >> 5;

    __shared__ float As[32][20];
    __shared__ float Bs[32][133];

    float acc[4][4];
#pragma unroll
    for (int i = 0; i < 4; i++)
#pragma unroll
        for (int g = 0; g < 4; g++) acc[i][g] = 0.f;

    for (int phase = 0; phase < 2; phase++) {
        const float* Ag = phase ? Hp : X;
        const float* Bg = phase ? Whh : Wih;
        const int K = phase ? H_ : Kx;
        const int ntiles = (K + 31) >> 5;
        for (int kt = 0; kt < ntiles; kt++) {
            const int kb = kt << 5;
            const bool ok = (kb + lane) < K;
#pragma unroll
            for (int i = 0; i < 4; i++) {
                int bb = wr + 4 * i;
                As[lane][bb] = ok ? Ag[(size_t)(b0 + bb) * K + kb + lane] : 0.f;
            }
#pragma unroll
            for (int i = 0; i < 32; i++) {
                int r = wr + 4 * i;
                int g = r >> 5, hh = r & 31;
                int row = g * H_ + h0 + hh;
                Bs[lane][r] = ok ? Bg[(size_t)row * K + kb + lane] : 0.f;
            }
            __syncthreads();
#pragma unroll
            for (int k = 0; k < 32; k++) {
                float4 av = *(const float4*)&As[k][bq * 4];
#pragma unroll
                for (int g = 0; g < 4; g++) {
                    float w = Bs[k][g * 32 + hl];
                    acc[0][g] += av.x * w;
                    acc[1][g] += av.y * w;
                    acc[2][g] += av.z * w;
                    acc[3][g] += av.w * w;
                }
            }
            __syncthreads();
        }
    }
    const int h = h0 + hl;
    const float bi0 = bih[h]          + bhh[h];
    const float bf  = bih[H_ + h]     + bhh[H_ + h];
    const float bg  = bih[2*H_ + h]   + bhh[2*H_ + h];
    const float bo  = bih[3*H_ + h]   + bhh[3*H_ + h];
#pragma unroll
    for (int bi = 0; bi < 4; bi++) {
        int b = b0 + bq * 4 + bi;
        float gi = acc[bi][0] + bi0;
        float gf = acc[bi][1] + bf;
        float gg = acc[bi][2] + bg;
        float go = acc[bi][3] + bo;
        float cp = Cp[b * H_ + h];
        float c2 = sig_fma(gf) * cp + sig_fma(gi) * tanh_fma(gg);
        float h2 = sig_fma(go) * tanh_fma(c2);
        Cout[b * H_ + h] = c2;
        Hout[b * H_ + h] = h2;
        if (Hcopy) Hcopy[(size_t)b * hstride + h] = h2;
    }
}

// ------------------------------- final output -------------------------------
__global__ void darnn_final(const float* __restrict__ h1f,
                            const float* __restrict__ partial,
                            const float* __restrict__ projW,
                            const float* __restrict__ projB,
                            float* __restrict__ out) {
    int b = blockIdx.x * blockDim.x + threadIdx.x;
    if (b < B_) {
        float acc = projB[0];
#pragma unroll 8
        for (int h = 0; h < H_; h++)
            acc += h1f[b * H_ + h] * projW[h] + partial[b * H_ + h] * projW[H_ + h];
        out[b] = acc;
    }
}

// --------------------------------- launcher ---------------------------------
extern "C" void kernel_launch(void* const* d_in, const int* in_sizes, int n_in,
                              void* d_out, int out_size) {
    const float* input    = (const float*)d_in[0];
    const float* eWih0    = (const float*)d_in[1];
    const float* eWhh0    = (const float*)d_in[2];
    const float* ebih0    = (const float*)d_in[3];
    const float* ebhh0    = (const float*)d_in[4];
    const float* eWih1    = (const float*)d_in[5];
    const float* eWhh1    = (const float*)d_in[6];
    const float* ebih1    = (const float*)d_in[7];
    const float* ebhh1    = (const float*)d_in[8];
    const float* dWih0    = (const float*)d_in[9];
    const float* dWhh0    = (const float*)d_in[10];
    const float* dbih0    = (const float*)d_in[11];
    const float* dbhh0    = (const float*)d_in[12];
    const float* dWih1    = (const float*)d_in[13];
    const float* dWhh1    = (const float*)d_in[14];
    const float* dbih1    = (const float*)d_in[15];
    const float* dbhh1    = (const float*)d_in[16];
    const float* attnW1   = (const float*)d_in[17];
    const float* attnB1   = (const float*)d_in[18];
    const float* attnW2   = (const float*)d_in[19];
    const float* attnB2   = (const float*)d_in[20];
    const float* attndW1  = (const float*)d_in[21];
    const float* attndB1  = (const float*)d_in[22];
    const float* attndW2  = (const float*)d_in[23];
    const float* attndB2  = (const float*)d_in[24];
    const float* decinW   = (const float*)d_in[25];
    const float* decinB   = (const float*)d_in[26];
    const float* projW    = (const float*)d_in[27];
    const float* projB    = (const float*)d_in[28];
    (void)in_sizes; (void)n_in; (void)out_size;

    float *st, *P, *P2, *hexp, *Hproj2, *W1Te, *W1Td, *xs, *din, *part;
    cudaGetSymbolAddress((void**)&st,     g_state);
    cudaGetSymbolAddress((void**)&P,      g_P);
    cudaGetSymbolAddress((void**)&P2,     g_P2);
    cudaGetSymbolAddress((void**)&hexp,   g_hexp);
    cudaGetSymbolAddress((void**)&Hproj2, g_Hproj2);
    cudaGetSymbolAddress((void**)&W1Te,   g_W1Te);
    cudaGetSymbolAddress((void**)&W1Td,   g_W1Td);
    cudaGetSymbolAddress((void**)&xs,     g_xs);
    cudaGetSymbolAddress((void**)&din,    g_din);
    cudaGetSymbolAddress((void**)&part,   g_partial);

    float* h0[2] = { st + 0 * SN, st + 1 * SN };
    float* c0[2] = { st + 2 * SN, st + 3 * SN };
    float* h1[2] = { st + 4 * SN, st + 5 * SN };
    float* c1[2] = { st + 6 * SN, st + 7 * SN };

    dim3 cellGrid(32, 4);

    darnn_prep<<<256, 256>>>(attnW1, attndW1, W1Te, W1Td, h0[0], c0[0], h1[0], c1[0]);
    darnn_penc<<<(B_ * E_) / 4, 256>>>(input, W1Te, attnB1, P);
    darnn_ptrans<<<B_ * 2, 256>>>(P, P2);

    for (int t = 0; t < T_; t++) {
        int p = t & 1, q = p ^ 1;
        darnn_enc_attn<<<B_, 512>>>(input, h1[p], c1[p], W1Te, attnW2, attnB2, P2, xs, t);
        darnn_lstm_cell<<<cellGrid, 128>>>(xs, E_, eWih0, h0[p], eWhh0, ebih0, ebhh0,
                                           c0[p], h0[q], c0[q], nullptr, 0);
        darnn_lstm_cell<<<cellGrid, 128>>>(h0[q], H_, eWih1, h1[p], eWhh1, ebih1, ebhh1,
                                           c1[p], h1[q], c1[q], hexp + (size_t)t * H_, T_ * H_);
    }

    darnn_hproj<<<(B_ * T_) / 16, 256>>>(hexp, W1Td, attndB1, Hproj2);
    darnn_zero_states<<<256, 256>>>(h0[0], c0[0], h1[0], c1[0]);

    for (int t = 0; t < T_; t++) {
        int p = t & 1, q = p ^ 1;
        darnn_dec_attn<<<B_, 512>>>(input, h1[p], c1[p], W1Td, attndW2, attndB2,
                                    Hproj2, hexp, decinW, decinB, din, part, t);
        darnn_lstm_cell<<<cellGrid, 128>>>(din, 1, dWih0, h0[p], dWhh0, dbih0, dbhh0,
                                           c0[p], h0[q], c0[q], nullptr, 0);
        darnn_lstm_cell<<<cellGrid, 128>>>(h0[q], H_, dWih1, h1[p], dWhh1, dbih1, dbhh1,
                                           c1[p], h1[q], c1[q], nullptr, 0);
    }

    darnn_final<<<4, 128>>>(h1[0], part, projW, projB, (float*)d_out);
}

// round 15
// speedup vs baseline: 1.7895x; 1.7895x over previous
#include <cuda_runtime.h>
#include <cstddef>
#include <cstdint>

#define B_  512
#define T_  64
#define I_  128
#define H_  128
#define E_  127

// ------------------------- device scratch (static) -------------------------
__device__ float g_P[(size_t)B_ * E_ * 64];
__device__ float g_P2[(size_t)B_ * 64 * 128];     // (b,j,e)
__device__ float g_hexp[(size_t)B_ * 64 * 128];   // (b,t,h)
__device__ float g_Hproj2[(size_t)B_ * 128 * 64]; // (b,j,t)
__device__ float g_W1Te[320 * 64];
__device__ float g_W1Td[384 * 128];
// cell weights transposed to [k(128)][512 rows]
__device__ float g_W0xE[128 * 512];
__device__ float g_W0hE[128 * 512];
__device__ float g_W1xE[128 * 512];
__device__ float g_W1hE[128 * 512];
__device__ float g_W0hD[128 * 512];
__device__ float g_W1xD[128 * 512];
__device__ float g_W1hD[128 * 512];
__device__ float g_bias[4 * 512];

// ------------------------------ math helpers -------------------------------
__device__ __forceinline__ float rcp_fast(float q) {
    float r = __uint_as_float(0x7EF311C3u - __float_as_uint(q));
    r = r * fmaf(-q, r, 2.0f);
    r = r * fmaf(-q, r, 2.0f);
    r = r * fmaf(-q, r, 2.0f);
    return r;
}
__device__ __forceinline__ float tanh_fma(float x) {
    const float kClamp = 7.90531110763549805f;
    x = fminf(fmaxf(x, -kClamp), kClamp);
    float x2 = x * x;
    float p = -2.76076847742355e-16f;
    p = fmaf(p, x2, 2.00018790482477e-13f);
    p = fmaf(p, x2, -8.60467152213735e-11f);
    p = fmaf(p, x2, 5.12229709037114e-08f);
    p = fmaf(p, x2, 1.48572235717979e-05f);
    p = fmaf(p, x2, 6.37261928875436e-04f);
    p = fmaf(p, x2, 4.89352455891786e-03f);
    p = x * p;
    float q = 1.19825839466702e-06f;
    q = fmaf(q, x2, 1.18534705686654e-04f);
    q = fmaf(q, x2, 2.26843463243900e-03f);
    q = fmaf(q, x2, 4.89352518554385e-03f);
    return p * rcp_fast(q);
}
__device__ __forceinline__ float sig_fma(float x) {
    return fmaf(tanh_fma(0.5f * x), 0.5f, 0.5f);
}
__device__ __forceinline__ float warp_sum(float v) {
#pragma unroll
    for (int o = 16; o; o >>= 1) v += __shfl_xor_sync(0xFFFFFFFFu, v, o);
    return v;
}
__device__ __forceinline__ float warp_max(float v) {
#pragma unroll
    for (int o = 16; o; o >>= 1) v = fmaxf(v, __shfl_xor_sync(0xFFFFFFFFu, v, o));
    return v;
}

// ----------------------------- prep (one-time) -----------------------------
__global__ void darnn_prep(const float* eWih0, const float* eWhh0,
                           const float* eWih1, const float* eWhh1,
                           const float* dWhh0, const float* dWih1, const float* dWhh1,
                           const float* ebih0, const float* ebhh0,
                           const float* ebih1, const float* ebhh1,
                           const float* dbih0, const float* dbhh0,
                           const float* dbih1, const float* dbhh1,
                           const float* aW1, const float* adW1) {
    const int N0 = 7 * 65536, N1 = 64 * 320, N2 = 128 * 384, N3 = 2048;
    for (int idx = blockIdx.x * blockDim.x + threadIdx.x; idx < N0 + N1 + N2 + N3;
         idx += gridDim.x * blockDim.x) {
        if (idx < N0) {
            int m = idx >> 16, r2 = idx & 65535;
            int k = r2 >> 9, r = r2 & 511;
            const float* src; float* dst; int K = 128;
            switch (m) {
                case 0: src = eWih0; dst = g_W0xE; K = 127; break;
                case 1: src = eWhh0; dst = g_W0hE; break;
                case 2: src = eWih1; dst = g_W1xE; break;
                case 3: src = eWhh1; dst = g_W1hE; break;
                case 4: src = dWhh0; dst = g_W0hD; break;
                case 5: src = dWih1; dst = g_W1xD; break;
                default: src = dWhh1; dst = g_W1hD; break;
            }
            dst[r2] = (k < K) ? src[r * K + k] : 0.f;
        } else if (idx < N0 + N1) {
            int i = idx - N0; int r = i / 320, c = i % 320;
            g_W1Te[c * 64 + r] = aW1[i];
        } else if (idx < N0 + N1 + N2) {
            int i = idx - N0 - N1; int r = i / 384, c = i % 384;
            g_W1Td[c * 128 + r] = adW1[i];
        } else {
            int i = idx - N0 - N1 - N2;
            int l = i >> 9, h = i & 511;
            const float* a; const float* b;
            switch (l) {
                case 0: a = ebih0; b = ebhh0; break;
                case 1: a = ebih1; b = ebhh1; break;
                case 2: a = dbih0; b = dbhh0; break;
                default: a = dbih1; b = dbhh1; break;
            }
            g_bias[i] = a[h] + b[h];
        }
    }
}

// ------------------ encoder attention pre-projection (once) ----------------
__global__ void darnn_penc(const float* __restrict__ input,
                           const float* __restrict__ W1T,
                           const float* __restrict__ b1,
                           float* __restrict__ P) {
    int row0 = blockIdx.x * 4;
    int tx = threadIdx.x;
    int j = tx & 63, r = tx >> 6;
    int row = row0 + r;
    int b = row / E_, e = row % E_;
    __shared__ float xsm[4][65];
    xsm[r][j] = input[((size_t)b * T_ + j) * I_ + 1 + e];
    __syncthreads();
    float acc = b1[j];
#pragma unroll 8
    for (int k = 0; k < 64; k++)
        acc += xsm[r][k] * W1T[(256 + k) * 64 + j];
    P[(size_t)row * 64 + j] = acc;
}

__global__ void darnn_ptrans(const float* __restrict__ P, float* __restrict__ P2) {
    int bb = blockIdx.x >> 1;
    int j0 = (blockIdx.x & 1) * 32;
    __shared__ float smT[128][33];
    int tx = threadIdx.x;
    int j = tx & 31, e0 = tx >> 5;
#pragma unroll
    for (int i = 0; i < 16; i++) {
        int e = e0 + 8 * i;
        smT[e][j] = (e < E_) ? P[((size_t)bb * E_ + e) * 64 + j0 + j] : 0.f;
    }
    __syncthreads();
    int e = tx & 127, jg = tx >> 7;
#pragma unroll
    for (int p = 0; p < 16; p++) {
        int jj = jg + 2 * p;
        P2[((size_t)bb * 64 + j0 + jj) * 128 + e] = smT[e][jj];
    }
}

// --------------- decoder attention pre-projection (b,j,t) ------------------
__global__ void darnn_hproj(const float* __restrict__ hexp,
                            const float* __restrict__ W1dT,
                            const float* __restrict__ b1d,
                            float* __restrict__ Hproj2) {
    int row0 = blockIdx.x * 16;
    int b = row0 >> 6, t0 = row0 & 63;
    int tx = threadIdx.x;
    int j = tx & 127, rs = tx >> 7;
    __shared__ float hs[16][129];
    __shared__ float outs[16][133];
#pragma unroll
    for (int i = 0; i < 8; i++) {
        int r = rs + 2 * i;
        hs[r][j] = hexp[((size_t)row0 + r) * H_ + j];
    }
    __syncthreads();
    float acc[8];
#pragma unroll
    for (int i = 0; i < 8; i++) acc[i] = b1d[j];
    for (int k = 0; k < 128; k++) {
        float w = W1dT[(256 + k) * 128 + j];
#pragma unroll
        for (int i = 0; i < 8; i++) acc[i] += hs[rs + 2 * i][k] * w;
    }
#pragma unroll
    for (int i = 0; i < 8; i++) outs[rs + 2 * i][j] = acc[i];
    __syncthreads();
    int t = tx & 15, jp = tx >> 4;
#pragma unroll
    for (int p = 0; p < 8; p++) {
        int jj = jp + 16 * p;
        Hproj2[((size_t)b * 128 + jj) * 64 + t0 + t] = outs[t][jj];
    }
}

// ------------------------ shared cell machinery ----------------------------
// WT: [128k][512r]; x4: smem [k*4+bi]; acc[a*4+bi] with a = row quad lane
__device__ __forceinline__ void cell_seg(const float* __restrict__ WT,
                                         const float* __restrict__ x4,
                                         int r4, int kh, float acc[16]) {
    const float4* W = reinterpret_cast<const float4*>(WT) + (size_t)(kh * 64) * 128 + r4;
    const float4* X = reinterpret_cast<const float4*>(x4) + kh * 64;
#pragma unroll 8
    for (int k = 0; k < 64; k++) {
        float4 w = W[(size_t)k * 128];
        float4 x = X[k];
        acc[0]  = fmaf(w.x, x.x, acc[0]);  acc[1]  = fmaf(w.x, x.y, acc[1]);
        acc[2]  = fmaf(w.x, x.z, acc[2]);  acc[3]  = fmaf(w.x, x.w, acc[3]);
        acc[4]  = fmaf(w.y, x.x, acc[4]);  acc[5]  = fmaf(w.y, x.y, acc[5]);
        acc[6]  = fmaf(w.y, x.z, acc[6]);  acc[7]  = fmaf(w.y, x.w, acc[7]);
        acc[8]  = fmaf(w.z, x.x, acc[8]);  acc[9]  = fmaf(w.z, x.y, acc[9]);
        acc[10] = fmaf(w.z, x.z, acc[10]); acc[11] = fmaf(w.z, x.w, acc[11]);
        acc[12] = fmaf(w.w, x.x, acc[12]); acc[13] = fmaf(w.w, x.y, acc[13]);
        acc[14] = fmaf(w.w, x.z, acc[14]); acc[15] = fmaf(w.w, x.w, acc[15]);
    }
}

__device__ __forceinline__ void cell_run(const float* WxT, const float* x4,
                                         const float* WhT, const float* h4,
                                         float* gat, int tx,
                                         const float* dW0T, const float* dins) {
    int r4 = tx & 127, kh = tx >> 7;
    float acc[16];
    if (dW0T && kh == 0) {
        float w0 = dW0T[4 * r4], w1 = dW0T[4 * r4 + 1];
        float w2 = dW0T[4 * r4 + 2], w3 = dW0T[4 * r4 + 3];
#pragma unroll
        for (int bi = 0; bi < 4; bi++) {
            float d = dins[bi];
            acc[0 + bi] = w0 * d; acc[4 + bi] = w1 * d;
            acc[8 + bi] = w2 * d; acc[12 + bi] = w3 * d;
        }
    } else {
#pragma unroll
        for (int i = 0; i < 16; i++) acc[i] = 0.f;
    }
    if (WxT) cell_seg(WxT, x4, r4, kh, acc);
    cell_seg(WhT, h4, r4, kh, acc);
    if (kh == 0) {
#pragma unroll
        for (int bi = 0; bi < 4; bi++)
            *reinterpret_cast<float4*>(&gat[bi * 512 + 4 * r4]) =
                make_float4(acc[0 + bi], acc[4 + bi], acc[8 + bi], acc[12 + bi]);
    }
    __syncthreads();
    if (kh == 1) {
#pragma unroll
        for (int bi = 0; bi < 4; bi++) {
            float4 g = *reinterpret_cast<float4*>(&gat[bi * 512 + 4 * r4]);
            g.x += acc[0 + bi]; g.y += acc[4 + bi];
            g.z += acc[8 + bi]; g.w += acc[12 + bi];
            *reinterpret_cast<float4*>(&gat[bi * 512 + 4 * r4]) = g;
        }
    }
    __syncthreads();
}

__device__ __forceinline__ void lstm_epi(const float* gat, const float* __restrict__ bias,
                                         float* c4, float* h4,
                                         float* hexp_g, int b0, int t, int tx) {
#pragma unroll
    for (int rep = 0; rep < 2; rep++) {
        int task = tx + rep * 256;
        int h = task & 127, bi = task >> 7;
        float gi = gat[bi * 512 + h]       + bias[h];
        float gf = gat[bi * 512 + 128 + h] + bias[128 + h];
        float gg = gat[bi * 512 + 256 + h] + bias[256 + h];
        float go = gat[bi * 512 + 384 + h] + bias[384 + h];
        float cp = c4[h * 4 + bi];
        float c2 = sig_fma(gf) * cp + sig_fma(gi) * tanh_fma(gg);
        float h2 = sig_fma(go) * tanh_fma(c2);
        c4[h * 4 + bi] = c2;
        h4[h * 4 + bi] = h2;
        if (hexp_g) hexp_g[((size_t)(b0 + bi) * 64 + t) * 128 + h] = h2;
    }
}

// ------------------------- persistent encoder ------------------------------
// smem floats: WB 17408 | h0s 512 | c0s 512 | h1s 512 | c1s 512 | xs 512 |
//              gat 2048 | hv 256 | W2s 64 | wred 32
__global__ __launch_bounds__(256, 1)
void darnn_enc(const float* __restrict__ input,
               const float* __restrict__ attnW1,
               const float* __restrict__ attnW2,
               const float* __restrict__ attnB2) {
    extern __shared__ float smf[];
    float* WB  = smf;
    float* h0s = smf + 17408;
    float* c0s = h0s + 512;
    float* h1s = c0s + 512;
    float* c1s = h1s + 512;
    float* xs  = c1s + 512;
    float* gat = xs + 512;
    float* hv  = gat + 2048;
    float* W2s = hv + 256;
    float* wred = W2s + 64;
    const int tx = threadIdx.x;
    const int b0 = blockIdx.x * 4;
    const float b2v = __ldg(attnB2);

    for (int i = tx; i < 64 * 256; i += 256) {
        int j = i >> 8, h = i & 255;
        WB[h * 68 + j] = attnW1[j * 320 + h];
    }
    if (tx < 64) W2s[tx] = attnW2[tx];
    for (int i = tx; i < 512 * 5; i += 256) h0s[i] = 0.f;  // states + xs
    __syncthreads();

    for (int t = 0; t < 64; t++) {
        // A: hv[bi*64+j]
        {
            int j = tx & 63, bi = tx >> 6;
            float a = 0.f;
#pragma unroll 8
            for (int h = 0; h < 128; h++)
                a += h1s[h * 4 + bi] * WB[h * 68 + j]
                   + c1s[h * 4 + bi] * WB[(128 + h) * 68 + j];
            hv[bi * 64 + j] = a;
        }
        __syncthreads();
        // B: logits + softmax + scaled input
        {
            int e0 = tx & 63, bi = tx >> 6;
            const float* Pb = g_P2 + (size_t)(b0 + bi) * 64 * 128;
            float lgA = b2v, lgB = b2v;
#pragma unroll 4
            for (int j = 0; j < 64; j++) {
                float pv = hv[bi * 64 + j], w = W2s[j];
                const float* pp = Pb + j * 128;
                lgA = fmaf(tanh_fma(pp[e0] + pv), w, lgA);
                lgB = fmaf(tanh_fma(pp[e0 + 64] + pv), w, lgB);
            }
            if (e0 == 63) lgB = -3.0e38f;
            int w = tx >> 5;
            float m = warp_max(fmaxf(lgA, lgB));
            if ((tx & 31) == 0) wred[w] = m;
            __syncthreads();
            m = fmaxf(wred[bi * 2], wred[bi * 2 + 1]);
            float eA = __expf(lgA - m);
            float eB = (e0 == 63) ? 0.f : __expf(lgB - m);
            float s = warp_sum(eA + eB);
            if ((tx & 31) == 0) wred[8 + w] = s;
            __syncthreads();
            float inv = 1.0f / (wred[8 + bi * 2] + wred[8 + bi * 2 + 1]);
            const float* xr = input + ((size_t)(b0 + bi) * 64 + t) * 128;
            xs[e0 * 4 + bi] = xr[1 + e0] * eA * inv;
            xs[(e0 + 64) * 4 + bi] = (e0 == 63) ? 0.f : xr[65 + e0] * eB * inv;
        }
        __syncthreads();
        // cells
        cell_run(g_W0xE, xs, g_W0hE, h0s, gat, tx, nullptr, nullptr);
        lstm_epi(gat, g_bias, c0s, h0s, nullptr, b0, t, tx);
        __syncthreads();
        cell_run(g_W1xE, h0s, g_W1hE, h1s, gat, tx, nullptr, nullptr);
        lstm_epi(gat, g_bias + 512, c1s, h1s, g_hexp, b0, t, tx);
        __syncthreads();
    }
}

// ------------------------- persistent decoder ------------------------------
// smem floats: WB 33792 | h0s..c1s 2048 | gat 2048 | hv 512 | a_s 256 |
//              pc 512 | dW0T 512 | dwin 132 | W2ds 128 | projs 257 | wred 32 | dins 4
__global__ __launch_bounds__(256, 1)
void darnn_dec(const float* __restrict__ input,
               const float* __restrict__ attndW1,
               const float* __restrict__ attndW2,
               const float* __restrict__ attndB2,
               const float* __restrict__ dWih0,
               const float* __restrict__ decinW,
               const float* __restrict__ decinB,
               const float* __restrict__ projW,
               const float* __restrict__ projB,
               float* __restrict__ out) {
    extern __shared__ float smf[];
    float* WB   = smf;
    float* h0s  = smf + 33792;
    float* c0s  = h0s + 512;
    float* h1s  = c0s + 512;
    float* c1s  = h1s + 512;
    float* gat  = c1s + 512;
    float* hv   = gat + 2048;
    float* a_s  = hv + 512;
    float* pc   = a_s + 256;
    float* dW0T = pc + 512;
    float* dwin = dW0T + 512;
    float* W2ds = dwin + 132;
    float* projs = W2ds + 128;
    float* wred = projs + 257;
    float* dins = wred + 32;
    const int tx = threadIdx.x;
    const int b0 = blockIdx.x * 4;
    const float b2dv = __ldg(attndB2);

    for (int i = tx; i < 128 * 256; i += 256) {
        int j = i >> 8, h = i & 255;
        WB[h * 132 + j] = attndW1[j * 384 + h];
    }
    if (tx < 128) W2ds[tx] = attndW2[tx];
    if (tx < 129) dwin[tx] = decinW[tx];
    if (tx == 129) dwin[129] = decinB[0];
    for (int i = tx; i < 512; i += 256) dW0T[i] = dWih0[i];
    for (int i = tx; i < 256; i += 256) { projs[i] = projW[i]; projs[i + ((tx==0)?256:0)] = (tx==0)? projB[0] : projs[i+0]; }
    if (tx == 0) projs[256] = projB[0];
    if (tx < 128) projs[128 + tx] = projW[128 + tx];
    if (tx < 128) projs[tx] = projW[tx];
    for (int i = tx; i < 2048; i += 256) h0s[i] = 0.f;
    __syncthreads();

    for (int t = 0; t < 64; t++) {
        // A: hv[bi*128+j]
        {
            int j = tx & 127, bh = tx >> 7;
            int biA = bh * 2, biB = bh * 2 + 1;
            float a0 = 0.f, a1 = 0.f;
#pragma unroll 8
            for (int h = 0; h < 128; h++) {
                float w1 = WB[h * 132 + j];
                float w2 = WB[(128 + h) * 132 + j];
                a0 += h1s[h * 4 + biA] * w1 + c1s[h * 4 + biA] * w2;
                a1 += h1s[h * 4 + biB] * w1 + c1s[h * 4 + biB] * w2;
            }
            hv[biA * 128 + j] = a0;
            hv[biB * 128 + j] = a1;
        }
        __syncthreads();
        // B: logits over tt + softmax
        {
            int tt = tx & 63, bi = tx >> 6;
            const float* Hp = g_Hproj2 + (size_t)(b0 + bi) * 128 * 64 + tt;
            float lg = b2dv;
#pragma unroll 4
            for (int j = 0; j < 128; j++)
                lg = fmaf(tanh_fma(Hp[j * 64] + hv[bi * 128 + j]), W2ds[j], lg);
            int w = tx >> 5;
            float m = warp_max(lg);
            if ((tx & 31) == 0) wred[w] = m;
            __syncthreads();
            m = fmaxf(wred[bi * 2], wred[bi * 2 + 1]);
            float ex = __expf(lg - m);
            float s = warp_sum(ex);
            if ((tx & 31) == 0) wred[8 + w] = s;
            __syncthreads();
            a_s[bi * 64 + tt] = ex / (wred[8 + bi * 2] + wred[8 + bi * 2 + 1]);
        }
        __syncthreads();
        // C: context + din
        {
            int h = tx & 127, bh = tx >> 7;
            int biA = bh * 2, biB = bh * 2 + 1;
            const float* ha = g_hexp + ((size_t)(b0 + biA) * 64) * 128 + h;
            const float* hb = g_hexp + ((size_t)(b0 + biB) * 64) * 128 + h;
            float p0 = 0.f, p1 = 0.f;
#pragma unroll 8
            for (int tt = 0; tt < 64; tt++) {
                p0 = fmaf(a_s[biA * 64 + tt], ha[tt * 128], p0);
                p1 = fmaf(a_s[biB * 64 + tt], hb[tt * 128], p1);
            }
            pc[h * 4 + biA] = p0;
            pc[h * 4 + biB] = p1;
        }
        __syncthreads();
        {
            int hh = tx & 63, bi = tx >> 6;
            float r = pc[hh * 4 + bi] * dwin[hh] + pc[(hh + 64) * 4 + bi] * dwin[hh + 64];
            r = warp_sum(r);
            if ((tx & 31) == 0) wred[tx >> 5] = r;
            __syncthreads();
            if (tx < 4)
                dins[tx] = wred[2 * tx] + wred[2 * tx + 1]
                         + dwin[128] * input[((size_t)(b0 + tx) * 64 + t) * 128]
                         + dwin[129];
        }
        __syncthreads();
        // cells
        cell_run(nullptr, nullptr, g_W0hD, h0s, gat, tx, dW0T, dins);
        lstm_epi(gat, g_bias + 1024, c0s, h0s, nullptr, b0, t, tx);
        __syncthreads();
        cell_run(g_W1xD, h0s, g_W1hD, h1s, gat, tx, nullptr, nullptr);
        lstm_epi(gat, g_bias + 1536, c1s, h1s, nullptr, b0, t, tx);
        __syncthreads();
    }
    // output projection
    {
        int hh = tx & 63, bi = tx >> 6;
        float r = h1s[hh * 4 + bi] * projs[hh]
                + h1s[(hh + 64) * 4 + bi] * projs[hh + 64]
                + pc[hh * 4 + bi] * projs[128 + hh]
                + pc[(hh + 64) * 4 + bi] * projs[192 + hh];
        r = warp_sum(r);
        if ((tx & 31) == 0) wred[tx >> 5] = r;
        __syncthreads();
        if (tx < 4)
            out[b0 + tx] = wred[2 * tx] + wred[2 * tx + 1] + projs[256];
    }
}

// --------------------------------- launcher ---------------------------------
extern "C" void kernel_launch(void* const* d_in, const int* in_sizes, int n_in,
                              void* d_out, int out_size) {
    const float* input    = (const float*)d_in[0];
    const float* eWih0    = (const float*)d_in[1];
    const float* eWhh0    = (const float*)d_in[2];
    const float* ebih0    = (const float*)d_in[3];
    const float* ebhh0    = (const float*)d_in[4];
    const float* eWih1    = (const float*)d_in[5];
    const float* eWhh1    = (const float*)d_in[6];
    const float* ebih1    = (const float*)d_in[7];
    const float* ebhh1    = (const float*)d_in[8];
    const float* dWih0    = (const float*)d_in[9];
    const float* dWhh0    = (const float*)d_in[10];
    const float* dbih0    = (const float*)d_in[11];
    const float* dbhh0    = (const float*)d_in[12];
    const float* dWih1    = (const float*)d_in[13];
    const float* dWhh1    = (const float*)d_in[14];
    const float* dbih1    = (const float*)d_in[15];
    const float* dbhh1    = (const float*)d_in[16];
    const float* attnW1   = (const float*)d_in[17];
    const float* attnB1   = (const float*)d_in[18];
    const float* attnW2   = (const float*)d_in[19];
    const float* attnB2   = (const float*)d_in[20];
    const float* attndW1  = (const float*)d_in[21];
    const float* attndB1  = (const float*)d_in[22];
    const float* attndW2  = (const float*)d_in[23];
    const float* attndB2  = (const float*)d_in[24];
    const float* decinW   = (const float*)d_in[25];
    const float* decinB   = (const float*)d_in[26];
    const float* projW    = (const float*)d_in[27];
    const float* projB    = (const float*)d_in[28];
    (void)in_sizes; (void)n_in; (void)out_size;

    float *P, *P2, *hexp, *Hproj2, *W1Te, *W1Td;
    cudaGetSymbolAddress((void**)&P,      g_P);
    cudaGetSymbolAddress((void**)&P2,     g_P2);
    cudaGetSymbolAddress((void**)&hexp,   g_hexp);
    cudaGetSymbolAddress((void**)&Hproj2, g_Hproj2);
    cudaGetSymbolAddress((void**)&W1Te,   g_W1Te);
    cudaGetSymbolAddress((void**)&W1Td,   g_W1Td);

    static bool attrDone = false;
    if (!attrDone) {
        cudaFuncSetAttribute(darnn_enc, cudaFuncAttributeMaxDynamicSharedMemorySize, 90 * 1024);
        cudaFuncSetAttribute(darnn_dec, cudaFuncAttributeMaxDynamicSharedMemorySize, 162 * 1024);
        attrDone = true;
    }

    darnn_prep<<<518, 1024>>>(eWih0, eWhh0, eWih1, eWhh1, dWhh0, dWih1, dWhh1,
                              ebih0, ebhh0, ebih1, ebhh1, dbih0, dbhh0, dbih1, dbhh1,
                              attnW1, attndW1);
    darnn_penc<<<(B_ * E_) / 4, 256>>>(input, W1Te, attnB1, P);
    darnn_ptrans<<<B_ * 2, 256>>>(P, P2);
    darnn_enc<<<128, 256, 90 * 1024>>>(input, attnW1, attnW2, attnB2);
    darnn_hproj<<<(B_ * T_) / 16, 256>>>(hexp, W1Td, attndB1, Hproj2);
    darnn_dec<<<128, 256, 162 * 1024>>>(input, attndW1, attndW2, attndB2,
                                        dWih0, decinW, decinB, projW, projB,
                                        (float*)d_out);
}

// round 16
// speedup vs baseline: 2.5813x; 1.4425x over previous
#include <cuda_runtime.h>
#include <cuda_fp16.h>
#include <cstddef>
#include <cstdint>

#define B_  512
#define T_  64
#define I_  128
#define H_  128
#define E_  127

// ------------------------- device scratch (static) -------------------------
__device__ float g_P[(size_t)B_ * E_ * 64];
__device__ float g_P2[(size_t)B_ * 64 * 128];     // (b,j,e)
__device__ float g_hexp[(size_t)B_ * 64 * 128];   // (b,t,h)
__device__ float g_Hproj2[(size_t)B_ * 128 * 64]; // (b,j,t)
__device__ float g_W1Te[320 * 64];
__device__ float g_W1Td[384 * 128];
// 7 cell weight matrices, fp16, layout [k(128)][512 rows]
// m: 0 W0xE 1 W0hE 2 W1xE 3 W1hE 4 W0hD 5 W1xD 6 W1hD
__device__ __half g_hW[7 * 128 * 512];
__device__ float g_bias[4 * 512];

// ------------------------------ math helpers -------------------------------
__device__ __forceinline__ float rcp_fast(float q) {
    float r = __uint_as_float(0x7EF311C3u - __float_as_uint(q));
    r = r * fmaf(-q, r, 2.0f);
    r = r * fmaf(-q, r, 2.0f);
    r = r * fmaf(-q, r, 2.0f);
    return r;
}
__device__ __forceinline__ float tanh_fma(float x) {
    const float kClamp = 7.90531110763549805f;
    x = fminf(fmaxf(x, -kClamp), kClamp);
    float x2 = x * x;
    float p = -2.76076847742355e-16f;
    p = fmaf(p, x2, 2.00018790482477e-13f);
    p = fmaf(p, x2, -8.60467152213735e-11f);
    p = fmaf(p, x2, 5.12229709037114e-08f);
    p = fmaf(p, x2, 1.48572235717979e-05f);
    p = fmaf(p, x2, 6.37261928875436e-04f);
    p = fmaf(p, x2, 4.89352455891786e-03f);
    p = x * p;
    float q = 1.19825839466702e-06f;
    q = fmaf(q, x2, 1.18534705686654e-04f);
    q = fmaf(q, x2, 2.26843463243900e-03f);
    q = fmaf(q, x2, 4.89352518554385e-03f);
    return p * rcp_fast(q);
}
__device__ __forceinline__ float sig_fma(float x) {
    return fmaf(tanh_fma(0.5f * x), 0.5f, 0.5f);
}
__device__ __forceinline__ float tanh_mufu(float x) {
    float y; asm("tanh.approx.f32 %0, %1;" : "=f"(y) : "f"(x)); return y;
}
__device__ __forceinline__ float warp_sum(float v) {
#pragma unroll
    for (int o = 16; o; o >>= 1) v += __shfl_xor_sync(0xFFFFFFFFu, v, o);
    return v;
}
__device__ __forceinline__ float warp_max(float v) {
#pragma unroll
    for (int o = 16; o; o >>= 1) v = fmaxf(v, __shfl_xor_sync(0xFFFFFFFFu, v, o));
    return v;
}
__device__ __forceinline__ float dot4(float4 a, float4 b) {
    return fmaf(a.x, b.x, fmaf(a.y, b.y, fmaf(a.z, b.z, a.w * b.w)));
}

// ----------------------------- prep (one-time) -----------------------------
__global__ void darnn_prep(const float* eWih0, const float* eWhh0,
                           const float* eWih1, const float* eWhh1,
                           const float* dWhh0, const float* dWih1, const float* dWhh1,
                           const float* ebih0, const float* ebhh0,
                           const float* ebih1, const float* ebhh1,
                           const float* dbih0, const float* dbhh0,
                           const float* dbih1, const float* dbhh1,
                           const float* aW1, const float* adW1) {
    const int N0 = 7 * 65536, N1 = 64 * 320, N2 = 128 * 384, N3 = 2048;
    for (int idx = blockIdx.x * blockDim.x + threadIdx.x; idx < N0 + N1 + N2 + N3;
         idx += gridDim.x * blockDim.x) {
        if (idx < N0) {
            int m = idx >> 16, r2 = idx & 65535;
            int k = r2 >> 9, r = r2 & 511;
            const float* src; int K = 128;
            switch (m) {
                case 0: src = eWih0; K = 127; break;
                case 1: src = eWhh0; break;
                case 2: src = eWih1; break;
                case 3: src = eWhh1; break;
                case 4: src = dWhh0; break;
                case 5: src = dWih1; break;
                default: src = dWhh1; break;
            }
            g_hW[idx] = __float2half((k < K) ? src[r * K + k] : 0.f);
        } else if (idx < N0 + N1) {
            int i = idx - N0; int r = i / 320, c = i % 320;
            g_W1Te[c * 64 + r] = aW1[i];
        } else if (idx < N0 + N1 + N2) {
            int i = idx - N0 - N1; int r = i / 384, c = i % 384;
            g_W1Td[c * 128 + r] = adW1[i];
        } else {
            int i = idx - N0 - N1 - N2;
            int l = i >> 9, h = i & 511;
            const float* a; const float* b;
            switch (l) {
                case 0: a = ebih0; b = ebhh0; break;
                case 1: a = ebih1; b = ebhh1; break;
                case 2: a = dbih0; b = dbhh0; break;
                default: a = dbih1; b = dbhh1; break;
            }
            g_bias[i] = a[h] + b[h];
        }
    }
}

// ------------------ encoder attention pre-projection (once) ----------------
__global__ void darnn_penc(const float* __restrict__ input,
                           const float* __restrict__ W1T,
                           const float* __restrict__ b1,
                           float* __restrict__ P) {
    int row0 = blockIdx.x * 4;
    int tx = threadIdx.x;
    int j = tx & 63, r = tx >> 6;
    int row = row0 + r;
    int b = row / E_, e = row % E_;
    __shared__ float xsm[4][65];
    xsm[r][j] = input[((size_t)b * T_ + j) * I_ + 1 + e];
    __syncthreads();
    float acc = b1[j];
#pragma unroll 8
    for (int k = 0; k < 64; k++)
        acc += xsm[r][k] * W1T[(256 + k) * 64 + j];
    P[(size_t)row * 64 + j] = acc;
}

__global__ void darnn_ptrans(const float* __restrict__ P, float* __restrict__ P2) {
    int bb = blockIdx.x >> 1;
    int j0 = (blockIdx.x & 1) * 32;
    __shared__ float smT[128][33];
    int tx = threadIdx.x;
    int j = tx & 31, e0 = tx >> 5;
#pragma unroll
    for (int i = 0; i < 16; i++) {
        int e = e0 + 8 * i;
        smT[e][j] = (e < E_) ? P[((size_t)bb * E_ + e) * 64 + j0 + j] : 0.f;
    }
    __syncthreads();
    int e = tx & 127, jg = tx >> 7;
#pragma unroll
    for (int p = 0; p < 16; p++) {
        int jj = jg + 2 * p;
        P2[((size_t)bb * 64 + j0 + jj) * 128 + e] = smT[e][jj];
    }
}

// --------------- decoder attention pre-projection (b,j,t) ------------------
__global__ void darnn_hproj(const float* __restrict__ hexp,
                            const float* __restrict__ W1dT,
                            const float* __restrict__ b1d,
                            float* __restrict__ Hproj2) {
    int row0 = blockIdx.x * 16;
    int b = row0 >> 6, t0 = row0 & 63;
    int tx = threadIdx.x;
    int j = tx & 127, rs = tx >> 7;
    __shared__ float hs[16][129];
    __shared__ float outs[16][133];
#pragma unroll
    for (int i = 0; i < 8; i++) {
        int r = rs + 2 * i;
        hs[r][j] = hexp[((size_t)row0 + r) * H_ + j];
    }
    __syncthreads();
    float acc[8];
#pragma unroll
    for (int i = 0; i < 8; i++) acc[i] = b1d[j];
    for (int k = 0; k < 128; k++) {
        float w = W1dT[(256 + k) * 128 + j];
#pragma unroll
        for (int i = 0; i < 8; i++) acc[i] += hs[rs + 2 * i][k] * w;
    }
#pragma unroll
    for (int i = 0; i < 8; i++) outs[rs + 2 * i][j] = acc[i];
    __syncthreads();
    int t = tx & 15, jp = tx >> 4;
#pragma unroll
    for (int p = 0; p < 8; p++) {
        int jj = jp + 16 * p;
        Hproj2[((size_t)b * 128 + jj) * 64 + t0 + t] = outs[t][jj];
    }
}

// ------------------------ cell machinery (512 thr) -------------------------
__device__ __forceinline__ void cell_seg_h(const __half* __restrict__ WT,
                                           const float* __restrict__ x4,
                                           int r4, int kq, float acc[16]) {
    const uint2* W = reinterpret_cast<const uint2*>(WT + (size_t)(kq * 32) * 512) + r4;
    const float4* X = reinterpret_cast<const float4*>(x4) + kq * 32;
#pragma unroll 8
    for (int k = 0; k < 32; k++) {
        uint2 u = W[(size_t)k * 128];
        float2 f01 = __half22float2(*reinterpret_cast<__half2*>(&u.x));
        float2 f23 = __half22float2(*reinterpret_cast<__half2*>(&u.y));
        float4 x = X[k];
        acc[0]  = fmaf(f01.x, x.x, acc[0]);  acc[1]  = fmaf(f01.x, x.y, acc[1]);
        acc[2]  = fmaf(f01.x, x.z, acc[2]);  acc[3]  = fmaf(f01.x, x.w, acc[3]);
        acc[4]  = fmaf(f01.y, x.x, acc[4]);  acc[5]  = fmaf(f01.y, x.y, acc[5]);
        acc[6]  = fmaf(f01.y, x.z, acc[6]);  acc[7]  = fmaf(f01.y, x.w, acc[7]);
        acc[8]  = fmaf(f23.x, x.x, acc[8]);  acc[9]  = fmaf(f23.x, x.y, acc[9]);
        acc[10] = fmaf(f23.x, x.z, acc[10]); acc[11] = fmaf(f23.x, x.w, acc[11]);
        acc[12] = fmaf(f23.y, x.x, acc[12]); acc[13] = fmaf(f23.y, x.y, acc[13]);
        acc[14] = fmaf(f23.y, x.z, acc[14]); acc[15] = fmaf(f23.y, x.w, acc[15]);
    }
}

__device__ __forceinline__ void cell_run4(const __half* WxT, const float* x4,
                                          const __half* WhT, const float* h4,
                                          float* gat4, int tx,
                                          const float* dW0T, const float* dins) {
    int r4 = tx & 127, kq = tx >> 7;
    float acc[16];
    if (dW0T && kq == 0) {
        float w0 = dW0T[4 * r4], w1 = dW0T[4 * r4 + 1];
        float w2 = dW0T[4 * r4 + 2], w3 = dW0T[4 * r4 + 3];
#pragma unroll
        for (int bi = 0; bi < 4; bi++) {
            float d = dins[bi];
            acc[0 + bi] = w0 * d; acc[4 + bi] = w1 * d;
            acc[8 + bi] = w2 * d; acc[12 + bi] = w3 * d;
        }
    } else {
#pragma unroll
        for (int i = 0; i < 16; i++) acc[i] = 0.f;
    }
    if (WxT) cell_seg_h(WxT, x4, r4, kq, acc);
    cell_seg_h(WhT, h4, r4, kq, acc);
    float* g = gat4 + kq * 2048;
#pragma unroll
    for (int bi = 0; bi < 4; bi++)
        *reinterpret_cast<float4*>(&g[bi * 512 + 4 * r4]) =
            make_float4(acc[0 + bi], acc[4 + bi], acc[8 + bi], acc[12 + bi]);
    __syncthreads();
}

__device__ __forceinline__ void lstm_epi4(const float* gat4, const float* __restrict__ bias,
                                          float* c4, float* h4, float* hB, float* cB,
                                          float* hexpg, int b0, int t, int tx) {
    int h = tx & 127, bi = tx >> 7;
    float gI = bias[h], gF = bias[128 + h], gG = bias[256 + h], gO = bias[384 + h];
#pragma unroll
    for (int q = 0; q < 4; q++) {
        const float* g = gat4 + q * 2048 + bi * 512;
        gI += g[h]; gF += g[128 + h]; gG += g[256 + h]; gO += g[384 + h];
    }
    float cp = c4[h * 4 + bi];
    float c2 = sig_fma(gF) * cp + sig_fma(gI) * tanh_fma(gG);
    float h2 = sig_fma(gO) * tanh_fma(c2);
    c4[h * 4 + bi] = c2;
    h4[h * 4 + bi] = h2;
    if (hB) { hB[bi * 128 + h] = h2; cB[bi * 128 + h] = c2; }
    if (hexpg) hexpg[((size_t)(b0 + bi) * 64 + t) * 128 + h] = h2;
}

// ------------------------- persistent encoder ------------------------------
__global__ __launch_bounds__(512, 1)
void darnn_enc(const float* __restrict__ input,
               const float* __restrict__ attnW1,
               const float* __restrict__ attnW2,
               const float* __restrict__ attnB2) {
    extern __shared__ float smf[];
    float* WB  = smf;             // [j<64][260]: attnW1[j][h<256]
    float* h0s = smf + 16640;
    float* c0s = h0s + 512;
    float* h1s = c0s + 512;
    float* c1s = h1s + 512;
    float* h1B = c1s + 512;       // [bi][128]
    float* c1B = h1B + 512;
    float* xs  = c1B + 512;       // [k][4]
    float* gat4 = xs + 512;       // 4 x [bi][512]
    float* hvp = gat4 + 8192;     // [8][256]
    float* hv  = hvp + 2048;      // [bi*64+j]
    float* W2s = hv + 256;
    float* wred = W2s + 64;       // 32
    const int tx = threadIdx.x;
    const int b0 = blockIdx.x * 4;
    const float b2v = __ldg(attnB2);

    for (int i = tx; i < 64 * 256; i += 512) {
        int j = i >> 8, h = i & 255;
        WB[j * 260 + h] = attnW1[j * 320 + h];
    }
    if (tx < 64) W2s[tx] = attnW2[tx];
    for (int i = tx; i < 3584; i += 512) h0s[i] = 0.f;   // states + B-copies + xs
    __syncthreads();

    for (int t = 0; t < 64; t++) {
        // A: partial hvec, 8 h-slices
        {
            int j = tx & 63, s = tx >> 6;
            const float* src = (s < 4) ? h1B : c1B;
            int off = (s & 3) * 32;
            const float4* Wr = reinterpret_cast<const float4*>(WB + j * 260 + s * 32);
            const float4* S0 = reinterpret_cast<const float4*>(src + off);
            const float4* S1 = reinterpret_cast<const float4*>(src + 128 + off);
            const float4* S2 = reinterpret_cast<const float4*>(src + 256 + off);
            const float4* S3 = reinterpret_cast<const float4*>(src + 384 + off);
            float a0 = 0, a1 = 0, a2 = 0, a3 = 0;
#pragma unroll
            for (int q = 0; q < 8; q++) {
                float4 w = Wr[q];
                a0 += dot4(w, S0[q]); a1 += dot4(w, S1[q]);
                a2 += dot4(w, S2[q]); a3 += dot4(w, S3[q]);
            }
            hvp[s * 256 + 0 * 64 + j] = a0;
            hvp[s * 256 + 1 * 64 + j] = a1;
            hvp[s * 256 + 2 * 64 + j] = a2;
            hvp[s * 256 + 3 * 64 + j] = a3;
        }
        __syncthreads();
        if (tx < 256) {
            float a = 0;
#pragma unroll
            for (int s = 0; s < 8; s++) a += hvp[s * 256 + tx];
            hv[tx] = a;
        }
        __syncthreads();
        // B: logits + softmax + scaled input
        {
            int e = tx & 127, bi = tx >> 7;
            bool valid = e < 127;
            const float* Pb = g_P2 + (size_t)(b0 + bi) * 8192 + e;
            float lg = b2v;
#pragma unroll 4
            for (int j = 0; j < 64; j++)
                lg = fmaf(tanh_mufu(Pb[j * 128] + hv[bi * 64 + j]), W2s[j], lg);
            if (!valid) lg = -3.0e38f;
            int w = tx >> 5;
            float m = warp_max(lg);
            if ((tx & 31) == 0) wred[w] = m;
            __syncthreads();
            m = fmaxf(fmaxf(wred[bi * 4], wred[bi * 4 + 1]),
                      fmaxf(wred[bi * 4 + 2], wred[bi * 4 + 3]));
            float ex = valid ? __expf(lg - m) : 0.f;
            float sm = warp_sum(ex);
            if ((tx & 31) == 0) wred[16 + w] = sm;
            __syncthreads();
            float inv = 1.0f / (wred[16 + bi * 4] + wred[16 + bi * 4 + 1]
                              + wred[16 + bi * 4 + 2] + wred[16 + bi * 4 + 3]);
            const float* xr = input + ((size_t)(b0 + bi) * 64 + t) * 128;
            xs[e * 4 + bi] = valid ? xr[1 + e] * ex * inv : 0.f;
        }
        __syncthreads();
        cell_run4(g_hW, xs, g_hW + 65536, h0s, gat4, tx, nullptr, nullptr);
        lstm_epi4(gat4, g_bias, c0s, h0s, nullptr, nullptr, nullptr, b0, t, tx);
        __syncthreads();
        cell_run4(g_hW + 2 * 65536, h0s, g_hW + 3 * 65536, h1s, gat4, tx, nullptr, nullptr);
        lstm_epi4(gat4, g_bias + 512, c1s, h1s, h1B, c1B, g_hexp, b0, t, tx);
        __syncthreads();
    }
}

// ------------------------- persistent decoder ------------------------------
__global__ __launch_bounds__(512, 1)
void darnn_dec(const float* __restrict__ input,
               const float* __restrict__ attndW1,
               const float* __restrict__ attndW2,
               const float* __restrict__ attndB2,
               const float* __restrict__ dWih0,
               const float* __restrict__ decinW,
               const float* __restrict__ decinB,
               const float* __restrict__ projW,
               const float* __restrict__ projB,
               float* __restrict__ out) {
    extern __shared__ float smf[];
    float* WB   = smf;            // [j<128][260]: attndW1[j][h<256]
    float* h0s  = smf + 33280;
    float* c0s  = h0s + 512;
    float* h1s  = c0s + 512;
    float* c1s  = h1s + 512;
    float* h1B  = c1s + 512;
    float* c1B  = h1B + 512;
    float* gat4 = c1B + 512;      // 8192
    float* hv   = gat4 + 8192;    // 512
    float* lgp  = hv + 512;       // 512
    float* a_s  = lgp + 512;      // 256
    float* pc   = a_s + 256;      // 512
    float* dW0T = pc + 512;       // 512
    float* dwin = dW0T + 512;     // 132
    float* W2ds = dwin + 132;     // 128
    float* projs = W2ds + 128;    // 257
    float* wred = projs + 257;    // 32
    float* dins = wred + 32;      // 4
    const int tx = threadIdx.x;
    const int b0 = blockIdx.x * 4;
    const float b2dv = __ldg(attndB2);

    for (int i = tx; i < 128 * 256; i += 512) {
        int j = i >> 8, h = i & 255;
        WB[j * 260 + h] = attndW1[j * 384 + h];
    }
    if (tx < 128) W2ds[tx] = attndW2[tx];
    if (tx < 129) dwin[tx] = decinW[tx];
    if (tx == 129) dwin[129] = decinB[0];
    if (tx < 256) projs[tx] = projW[tx];
    if (tx == 0) projs[256] = projB[0];
    if (tx < 512) dW0T[tx] = dWih0[tx];
    for (int i = tx; i < 3072; i += 512) h0s[i] = 0.f;
    __syncthreads();

    for (int t = 0; t < 64; t++) {
        // A: hv[bi*128+j]
        {
            int j = tx & 127, bi = tx >> 7;
            const float4* Wr = reinterpret_cast<const float4*>(WB + j * 260);
            const float4* Hh = reinterpret_cast<const float4*>(h1B + bi * 128);
            const float4* Cc = reinterpret_cast<const float4*>(c1B + bi * 128);
            float a = 0;
#pragma unroll 8
            for (int q = 0; q < 32; q++)
                a += dot4(Wr[q], Hh[q]) + dot4(Wr[32 + q], Cc[q]);
            hv[bi * 128 + j] = a;
        }
        __syncthreads();
        // B: logits (j split 2-way) + softmax
        {
            int tt = tx & 63, bi = (tx >> 6) & 3, jh = tx >> 8;
            const float* Hp = g_Hproj2 + (size_t)(b0 + bi) * 8192 + tt;
            float lg = 0;
#pragma unroll 4
            for (int jj = 0; jj < 64; jj++) {
                int j = jh * 64 + jj;
                lg = fmaf(tanh_mufu(Hp[j * 64] + hv[bi * 128 + j]), W2ds[j], lg);
            }
            lgp[jh * 256 + bi * 64 + tt] = lg;
        }
        __syncthreads();
        {
            bool act = tx < 256;
            int bi = (tx >> 6) & 3;
            float lg = act ? (lgp[tx] + lgp[256 + tx] + b2dv) : -3.0e38f;
            int w = tx >> 5;
            float m = warp_max(lg);
            if ((tx & 31) == 0) wred[w] = m;
            __syncthreads();
            m = fmaxf(wred[bi * 2], wred[bi * 2 + 1]);
            float ex = act ? __expf(lg - m) : 0.f;
            float sm = warp_sum(ex);
            if ((tx & 31) == 0) wred[16 + w] = sm;
            __syncthreads();
            if (act)
                a_s[tx] = ex / (wred[16 + bi * 2] + wred[16 + bi * 2 + 1]);
        }
        __syncthreads();
        // C: context
        {
            int h = tx & 127, bi = tx >> 7;
            const float* hx = g_hexp + ((size_t)(b0 + bi) * 64) * 128 + h;
            float p = 0;
#pragma unroll 8
            for (int tt = 0; tt < 64; tt++)
                p = fmaf(a_s[bi * 64 + tt], hx[tt * 128], p);
            pc[h * 4 + bi] = p;
        }
        __syncthreads();
        // din
        {
            float r = 0;
            if (tx < 256) {
                int hh = tx & 63, bi = tx >> 6;
                r = pc[hh * 4 + bi] * dwin[hh] + pc[(hh + 64) * 4 + bi] * dwin[hh + 64];
            }
            r = warp_sum(r);
            if ((tx & 31) == 0) wred[tx >> 5] = r;
            __syncthreads();
            if (tx < 4)
                dins[tx] = wred[2 * tx] + wred[2 * tx + 1]
                         + dwin[128] * input[((size_t)(b0 + tx) * 64 + t) * 128]
                         + dwin[129];
        }
        __syncthreads();
        cell_run4(nullptr, nullptr, g_hW + 4 * 65536, h0s, gat4, tx, dW0T, dins);
        lstm_epi4(gat4, g_bias + 1024, c0s, h0s, nullptr, nullptr, nullptr, b0, t, tx);
        __syncthreads();
        cell_run4(g_hW + 5 * 65536, h0s, g_hW + 6 * 65536, h1s, gat4, tx, nullptr, nullptr);
        lstm_epi4(gat4, g_bias + 1536, c1s, h1s, h1B, c1B, nullptr, b0, t, tx);
        __syncthreads();
    }
    // output projection
    {
        float r = 0;
        if (tx < 256) {
            int hh = tx & 63, bi = tx >> 6;
            r = h1s[hh * 4 + bi] * projs[hh]
              + h1s[(hh + 64) * 4 + bi] * projs[hh + 64]
              + pc[hh * 4 + bi] * projs[128 + hh]
              + pc[(hh + 64) * 4 + bi] * projs[192 + hh];
        }
        r = warp_sum(r);
        if ((tx & 31) == 0) wred[tx >> 5] = r;
        __syncthreads();
        if (tx < 4)
            out[b0 + tx] = wred[2 * tx] + wred[2 * tx + 1] + projs[256];
    }
}

// --------------------------------- launcher ---------------------------------
extern "C" void kernel_launch(void* const* d_in, const int* in_sizes, int n_in,
                              void* d_out, int out_size) {
    const float* input    = (const float*)d_in[0];
    const float* eWih0    = (const float*)d_in[1];
    const float* eWhh0    = (const float*)d_in[2];
    const float* ebih0    = (const float*)d_in[3];
    const float* ebhh0    = (const float*)d_in[4];
    const float* eWih1    = (const float*)d_in[5];
    const float* eWhh1    = (const float*)d_in[6];
    const float* ebih1    = (const float*)d_in[7];
    const float* ebhh1    = (const float*)d_in[8];
    const float* dWih0    = (const float*)d_in[9];
    const float* dWhh0    = (const float*)d_in[10];
    const float* dbih0    = (const float*)d_in[11];
    const float* dbhh0    = (const float*)d_in[12];
    const float* dWih1    = (const float*)d_in[13];
    const float* dWhh1    = (const float*)d_in[14];
    const float* dbih1    = (const float*)d_in[15];
    const float* dbhh1    = (const float*)d_in[16];
    const float* attnW1   = (const float*)d_in[17];
    const float* attnB1   = (const float*)d_in[18];
    const float* attnW2   = (const float*)d_in[19];
    const float* attnB2   = (const float*)d_in[20];
    const float* attndW1  = (const float*)d_in[21];
    const float* attndB1  = (const float*)d_in[22];
    const float* attndW2  = (const float*)d_in[23];
    const float* attndB2  = (const float*)d_in[24];
    const float* decinW   = (const float*)d_in[25];
    const float* decinB   = (const float*)d_in[26];
    const float* projW    = (const float*)d_in[27];
    const float* projB    = (const float*)d_in[28];
    (void)in_sizes; (void)n_in; (void)out_size;

    float *P, *P2, *hexp, *Hproj2, *W1Te, *W1Td;
    cudaGetSymbolAddress((void**)&P,      g_P);
    cudaGetSymbolAddress((void**)&P2,     g_P2);
    cudaGetSymbolAddress((void**)&hexp,   g_hexp);
    cudaGetSymbolAddress((void**)&Hproj2, g_Hproj2);
    cudaGetSymbolAddress((void**)&W1Te,   g_W1Te);
    cudaGetSymbolAddress((void**)&W1Td,   g_W1Td);

    static bool attrDone = false;
    if (!attrDone) {
        cudaFuncSetAttribute(darnn_enc, cudaFuncAttributeMaxDynamicSharedMemorySize, 126 * 1024);
        cudaFuncSetAttribute(darnn_dec, cudaFuncAttributeMaxDynamicSharedMemorySize, 190 * 1024);
        attrDone = true;
    }

    darnn_prep<<<518, 1024>>>(eWih0, eWhh0, eWih1, eWhh1, dWhh0, dWih1, dWhh1,
                              ebih0, ebhh0, ebih1, ebhh1, dbih0, dbhh0, dbih1, dbhh1,
                              attnW1, attndW1);
    darnn_penc<<<(B_ * E_) / 4, 256>>>(input, W1Te, attnB1, P);
    darnn_ptrans<<<B_ * 2, 256>>>(P, P2);
    darnn_enc<<<128, 512, 126 * 1024>>>(input, attnW1, attnW2, attnB2);
    darnn_hproj<<<(B_ * T_) / 16, 256>>>(hexp, W1Td, attndB1, Hproj2);
    darnn_dec<<<128, 512, 190 * 1024>>>(input, attndW1, attndW2, attndB2,
                                        dWih0, decinW, decinB, projW, projB,
                                        (float*)d_out);
}

// round 17
// speedup vs baseline: 2.6289x; 1.0185x over previous
#include <cuda_runtime.h>
#include <cuda_fp16.h>
#include <cstddef>
#include <cstdint>

#define B_  512
#define T_  64
#define I_  128
#define H_  128
#define E_  127

// ------------------------- device scratch (static) -------------------------
__device__ float g_P[(size_t)B_ * E_ * 64];
__device__ float g_P2[(size_t)B_ * 64 * 128];     // (b,j,e)
__device__ float g_hexp[(size_t)B_ * 64 * 128];   // (b,t,h)
__device__ float g_Hproj2[(size_t)B_ * 128 * 64]; // (b,j,t)
__device__ float g_W1Te[320 * 64];
__device__ float g_W1Td[384 * 128];
// 7 cell weight matrices, fp16, layout [k(128)][512 rows]
// m: 0 W0xE 1 W0hE 2 W1xE 3 W1hE 4 W0hD 5 W1xD 6 W1hD
__device__ __half g_hW[7 * 128 * 512];
__device__ float g_bias[4 * 512];

// ------------------------------ math helpers -------------------------------
__device__ __forceinline__ float rcp_fast(float q) {
    float r = __uint_as_float(0x7EF311C3u - __float_as_uint(q));
    r = r * fmaf(-q, r, 2.0f);
    r = r * fmaf(-q, r, 2.0f);
    r = r * fmaf(-q, r, 2.0f);
    return r;
}
__device__ __forceinline__ float tanh_fma(float x) {
    const float kClamp = 7.90531110763549805f;
    x = fminf(fmaxf(x, -kClamp), kClamp);
    float x2 = x * x;
    float p = -2.76076847742355e-16f;
    p = fmaf(p, x2, 2.00018790482477e-13f);
    p = fmaf(p, x2, -8.60467152213735e-11f);
    p = fmaf(p, x2, 5.12229709037114e-08f);
    p = fmaf(p, x2, 1.48572235717979e-05f);
    p = fmaf(p, x2, 6.37261928875436e-04f);
    p = fmaf(p, x2, 4.89352455891786e-03f);
    p = x * p;
    float q = 1.19825839466702e-06f;
    q = fmaf(q, x2, 1.18534705686654e-04f);
    q = fmaf(q, x2, 2.26843463243900e-03f);
    q = fmaf(q, x2, 4.89352518554385e-03f);
    return p * rcp_fast(q);
}
__device__ __forceinline__ float sig_fma(float x) {
    return fmaf(tanh_fma(0.5f * x), 0.5f, 0.5f);
}
__device__ __forceinline__ float tanh_mufu(float x) {
    float y; asm("tanh.approx.f32 %0, %1;" : "=f"(y) : "f"(x)); return y;
}
__device__ __forceinline__ float warp_sum(float v) {
#pragma unroll
    for (int o = 16; o; o >>= 1) v += __shfl_xor_sync(0xFFFFFFFFu, v, o);
    return v;
}
__device__ __forceinline__ float warp_max(float v) {
#pragma unroll
    for (int o = 16; o; o >>= 1) v = fmaxf(v, __shfl_xor_sync(0xFFFFFFFFu, v, o));
    return v;
}
__device__ __forceinline__ float dot4(float4 a, float4 b) {
    return fmaf(a.x, b.x, fmaf(a.y, b.y, fmaf(a.z, b.z, a.w * b.w)));
}

// ----------------------------- prep (one-time) -----------------------------
__global__ void darnn_prep(const float* eWih0, const float* eWhh0,
                           const float* eWih1, const float* eWhh1,
                           const float* dWhh0, const float* dWih1, const float* dWhh1,
                           const float* ebih0, const float* ebhh0,
                           const float* ebih1, const float* ebhh1,
                           const float* dbih0, const float* dbhh0,
                           const float* dbih1, const float* dbhh1,
                           const float* aW1, const float* adW1) {
    const int N0 = 7 * 65536, N1 = 64 * 320, N2 = 128 * 384, N3 = 2048;
    for (int idx = blockIdx.x * blockDim.x + threadIdx.x; idx < N0 + N1 + N2 + N3;
         idx += gridDim.x * blockDim.x) {
        if (idx < N0) {
            int m = idx >> 16, r2 = idx & 65535;
            int k = r2 >> 9, r = r2 & 511;
            const float* src; int K = 128;
            switch (m) {
                case 0: src = eWih0; K = 127; break;
                case 1: src = eWhh0; break;
                case 2: src = eWih1; break;
                case 3: src = eWhh1; break;
                case 4: src = dWhh0; break;
                case 5: src = dWih1; break;
                default: src = dWhh1; break;
            }
            g_hW[idx] = __float2half((k < K) ? src[r * K + k] : 0.f);
        } else if (idx < N0 + N1) {
            int i = idx - N0; int r = i / 320, c = i % 320;
            g_W1Te[c * 64 + r] = aW1[i];
        } else if (idx < N0 + N1 + N2) {
            int i = idx - N0 - N1; int r = i / 384, c = i % 384;
            g_W1Td[c * 128 + r] = adW1[i];
        } else {
            int i = idx - N0 - N1 - N2;
            int l = i >> 9, h = i & 511;
            const float* a; const float* b;
            switch (l) {
                case 0: a = ebih0; b = ebhh0; break;
                case 1: a = ebih1; b = ebhh1; break;
                case 2: a = dbih0; b = dbhh0; break;
                default: a = dbih1; b = dbhh1; break;
            }
            g_bias[i] = a[h] + b[h];
        }
    }
}

// ------------------ encoder attention pre-projection (once) ----------------
__global__ void darnn_penc(const float* __restrict__ input,
                           const float* __restrict__ W1T,
                           const float* __restrict__ b1,
                           float* __restrict__ P) {
    int row0 = blockIdx.x * 4;
    int tx = threadIdx.x;
    int j = tx & 63, r = tx >> 6;
    int row = row0 + r;
    int b = row / E_, e = row % E_;
    __shared__ float xsm[4][65];
    xsm[r][j] = input[((size_t)b * T_ + j) * I_ + 1 + e];
    __syncthreads();
    float acc = b1[j];
#pragma unroll 8
    for (int k = 0; k < 64; k++)
        acc += xsm[r][k] * W1T[(256 + k) * 64 + j];
    P[(size_t)row * 64 + j] = acc;
}

__global__ void darnn_ptrans(const float* __restrict__ P, float* __restrict__ P2) {
    int bb = blockIdx.x >> 1;
    int j0 = (blockIdx.x & 1) * 32;
    __shared__ float smT[128][33];
    int tx = threadIdx.x;
    int j = tx & 31, e0 = tx >> 5;
#pragma unroll
    for (int i = 0; i < 16; i++) {
        int e = e0 + 8 * i;
        smT[e][j] = (e < E_) ? P[((size_t)bb * E_ + e) * 64 + j0 + j] : 0.f;
    }
    __syncthreads();
    int e = tx & 127, jg = tx >> 7;
#pragma unroll
    for (int p = 0; p < 16; p++) {
        int jj = jg + 2 * p;
        P2[((size_t)bb * 64 + j0 + jj) * 128 + e] = smT[e][jj];
    }
}

// --------------- decoder attention pre-projection (b,j,t) ------------------
__global__ void darnn_hproj(const float* __restrict__ hexp,
                            const float* __restrict__ W1dT,
                            const float* __restrict__ b1d,
                            float* __restrict__ Hproj2) {
    int row0 = blockIdx.x * 16;
    int b = row0 >> 6, t0 = row0 & 63;
    int tx = threadIdx.x;
    int j = tx & 127, rs = tx >> 7;
    __shared__ float hs[16][129];
    __shared__ float outs[16][133];
#pragma unroll
    for (int i = 0; i < 8; i++) {
        int r = rs + 2 * i;
        hs[r][j] = hexp[((size_t)row0 + r) * H_ + j];
    }
    __syncthreads();
    float acc[8];
#pragma unroll
    for (int i = 0; i < 8; i++) acc[i] = b1d[j];
    for (int k = 0; k < 128; k++) {
        float w = W1dT[(256 + k) * 128 + j];
#pragma unroll
        for (int i = 0; i < 8; i++) acc[i] += hs[rs + 2 * i][k] * w;
    }
#pragma unroll
    for (int i = 0; i < 8; i++) outs[rs + 2 * i][j] = acc[i];
    __syncthreads();
    int t = tx & 15, jp = tx >> 4;
#pragma unroll
    for (int p = 0; p < 8; p++) {
        int jj = jp + 16 * p;
        Hproj2[((size_t)b * 128 + jj) * 64 + t0 + t] = outs[t][jj];
    }
}

// ------------------------ cell machinery (1024 thr) ------------------------
// processes 16 consecutive k starting at k0
__device__ __forceinline__ void cell_seg16(const __half* __restrict__ WT,
                                           const float* __restrict__ x4,
                                           int r4, int k0, float acc[16]) {
    const uint2* W = reinterpret_cast<const uint2*>(WT + (size_t)k0 * 512) + r4;
    const float4* X = reinterpret_cast<const float4*>(x4) + k0;
#pragma unroll
    for (int k = 0; k < 16; k++) {
        uint2 u = W[(size_t)k * 128];
        float2 f01 = __half22float2(*reinterpret_cast<__half2*>(&u.x));
        float2 f23 = __half22float2(*reinterpret_cast<__half2*>(&u.y));
        float4 x = X[k];
        acc[0]  = fmaf(f01.x, x.x, acc[0]);  acc[1]  = fmaf(f01.x, x.y, acc[1]);
        acc[2]  = fmaf(f01.x, x.z, acc[2]);  acc[3]  = fmaf(f01.x, x.w, acc[3]);
        acc[4]  = fmaf(f01.y, x.x, acc[4]);  acc[5]  = fmaf(f01.y, x.y, acc[5]);
        acc[6]  = fmaf(f01.y, x.z, acc[6]);  acc[7]  = fmaf(f01.y, x.w, acc[7]);
        acc[8]  = fmaf(f23.x, x.x, acc[8]);  acc[9]  = fmaf(f23.x, x.y, acc[9]);
        acc[10] = fmaf(f23.x, x.z, acc[10]); acc[11] = fmaf(f23.x, x.w, acc[11]);
        acc[12] = fmaf(f23.y, x.x, acc[12]); acc[13] = fmaf(f23.y, x.y, acc[13]);
        acc[14] = fmaf(f23.y, x.z, acc[14]); acc[15] = fmaf(f23.y, x.w, acc[15]);
    }
}

// 8 kq groups, two-phase accumulation into 4 gat partials
__device__ __forceinline__ void cell_run8(const __half* WxT, const float* x4,
                                          const __half* WhT, const float* h4,
                                          float* gat4, int tx,
                                          const float* dW0T, const float* dins) {
    int r4 = tx & 127, kq = tx >> 7;     // kq 0..7
    float acc[16];
    if (dW0T && kq == 0) {
        float w0 = dW0T[4 * r4], w1 = dW0T[4 * r4 + 1];
        float w2 = dW0T[4 * r4 + 2], w3 = dW0T[4 * r4 + 3];
#pragma unroll
        for (int bi = 0; bi < 4; bi++) {
            float d = dins[bi];
            acc[0 + bi] = w0 * d; acc[4 + bi] = w1 * d;
            acc[8 + bi] = w2 * d; acc[12 + bi] = w3 * d;
        }
    } else {
#pragma unroll
        for (int i = 0; i < 16; i++) acc[i] = 0.f;
    }
    int k0 = kq * 16;
    if (WxT) cell_seg16(WxT, x4, r4, k0, acc);
    cell_seg16(WhT, h4, r4, k0, acc);
    float* g = gat4 + (kq & 3) * 2048;
    if (kq < 4) {
#pragma unroll
        for (int bi = 0; bi < 4; bi++)
            *reinterpret_cast<float4*>(&g[bi * 512 + 4 * r4]) =
                make_float4(acc[0 + bi], acc[4 + bi], acc[8 + bi], acc[12 + bi]);
    }
    __syncthreads();
    if (kq >= 4) {
#pragma unroll
        for (int bi = 0; bi < 4; bi++) {
            float4 v = *reinterpret_cast<float4*>(&g[bi * 512 + 4 * r4]);
            v.x += acc[0 + bi]; v.y += acc[4 + bi];
            v.z += acc[8 + bi]; v.w += acc[12 + bi];
            *reinterpret_cast<float4*>(&g[bi * 512 + 4 * r4]) = v;
        }
    }
    __syncthreads();
}

__device__ __forceinline__ void lstm_epi8(const float* gat4, const float* __restrict__ bias,
                                          float* c4, float* h4, float* hB, float* cB,
                                          float* hexpg, int b0, int t, int tx) {
    if (tx < 512) {
        int h = tx & 127, bi = tx >> 7;
        float gI = bias[h], gF = bias[128 + h], gG = bias[256 + h], gO = bias[384 + h];
#pragma unroll
        for (int q = 0; q < 4; q++) {
            const float* g = gat4 + q * 2048 + bi * 512;
            gI += g[h]; gF += g[128 + h]; gG += g[256 + h]; gO += g[384 + h];
        }
        float cp = c4[h * 4 + bi];
        float c2 = sig_fma(gF) * cp + sig_fma(gI) * tanh_fma(gG);
        float h2 = sig_fma(gO) * tanh_fma(c2);
        c4[h * 4 + bi] = c2;
        h4[h * 4 + bi] = h2;
        if (hB) { hB[bi * 128 + h] = h2; cB[bi * 128 + h] = c2; }
        if (hexpg) hexpg[((size_t)(b0 + bi) * 64 + t) * 128 + h] = h2;
    }
}

// ------------------------- persistent encoder ------------------------------
__global__ __launch_bounds__(1024, 1)
void darnn_enc(const float* __restrict__ input,
               const float* __restrict__ attnW1,
               const float* __restrict__ attnW2,
               const float* __restrict__ attnB2) {
    extern __shared__ float smf[];
    float* WB   = smf;              // [j<64][260] attnW1 rows (cols 0..255)
    float* h0s  = smf + 16640;      // [h*4+bi]
    float* c0s  = h0s + 512;
    float* h1s  = c0s + 512;
    float* c1s  = h1s + 512;
    float* h1B  = c1s + 512;        // [bi*128+h]
    float* c1B  = h1B + 512;
    float* xs   = c1B + 512;        // [k*4+bi]
    float* gat4 = xs + 512;         // 4 x [bi][512]
    float* hvp  = gat4 + 8192;      // 16 x 256
    float* hv   = hvp + 4096;       // [bi*64+j]
    float* lgp  = hv + 256;         // 2 x 512
    float* W2s  = lgp + 1024;       // 64
    float* wred = W2s + 64;         // 32
    const int tx = threadIdx.x;
    const int b0 = blockIdx.x * 4;
    const float b2v = __ldg(attnB2);

    for (int i = tx; i < 64 * 256; i += 1024) {
        int j = i >> 8, h = i & 255;
        WB[j * 260 + h] = attnW1[j * 320 + h];
    }
    if (tx < 64) W2s[tx] = attnW2[tx];
    for (int i = tx; i < 3584; i += 1024) h0s[i] = 0.f;   // states + B copies + xs
    __syncthreads();

    for (int t = 0; t < 64; t++) {
        // A: hvec partials, 16 slices of the 256-long [h1|c1] vector
        {
            int j = tx & 63, s = tx >> 6;
            const float* src = ((s < 8) ? h1B : c1B) + (s & 7) * 16;
            const float4* Wr = reinterpret_cast<const float4*>(WB + j * 260 + s * 16);
#pragma unroll
            for (int bi = 0; bi < 4; bi++) {
                const float4* S = reinterpret_cast<const float4*>(src + bi * 128);
                float a = dot4(Wr[0], S[0]) + dot4(Wr[1], S[1])
                        + dot4(Wr[2], S[2]) + dot4(Wr[3], S[3]);
                hvp[s * 256 + bi * 64 + j] = a;
            }
        }
        __syncthreads();
        if (tx < 256) {
            float a = 0.f;
#pragma unroll
            for (int s = 0; s < 16; s++) a += hvp[s * 256 + tx];
            hv[tx] = a;
        }
        __syncthreads();
        // B1: logit partials, j split 2-way
        {
            int e = tx & 127, bi = (tx >> 7) & 3, jh = tx >> 9;
            const float* Pb = g_P2 + (size_t)(b0 + bi) * 8192 + e;
            float lg = 0.f;
#pragma unroll 4
            for (int jj = 0; jj < 32; jj++) {
                int j = jh * 32 + jj;
                lg = fmaf(tanh_mufu(Pb[j * 128] + hv[bi * 64 + j]), W2s[j], lg);
            }
            lgp[jh * 512 + bi * 128 + e] = lg;
        }
        __syncthreads();
        // B2: combine + softmax + scaled input
        {
            bool act = tx < 512;
            int e = tx & 127, bi = (tx >> 7) & 3, w = tx >> 5;
            float lg = -3.0e38f;
            if (act) {
                lg = lgp[tx] + lgp[512 + tx] + b2v;
                if (e >= 127) lg = -3.0e38f;
            }
            float m = warp_max(lg);
            if (act && (tx & 31) == 0) wred[w] = m;
            __syncthreads();
            m = fmaxf(fmaxf(wred[bi * 4], wred[bi * 4 + 1]),
                      fmaxf(wred[bi * 4 + 2], wred[bi * 4 + 3]));
            float ex = (act && e < 127) ? __expf(lg - m) : 0.f;
            float sm = warp_sum(ex);
            if (act && (tx & 31) == 0) wred[16 + w] = sm;
            __syncthreads();
            if (act) {
                float inv = 1.0f / (wred[16 + bi * 4] + wred[16 + bi * 4 + 1]
                                  + wred[16 + bi * 4 + 2] + wred[16 + bi * 4 + 3]);
                const float* xr = input + ((size_t)(b0 + bi) * 64 + t) * 128;
                xs[e * 4 + bi] = (e < 127) ? xr[1 + e] * ex * inv : 0.f;
            }
        }
        __syncthreads();
        cell_run8(g_hW, xs, g_hW + 65536, h0s, gat4, tx, nullptr, nullptr);
        lstm_epi8(gat4, g_bias, c0s, h0s, nullptr, nullptr, nullptr, b0, t, tx);
        __syncthreads();
        cell_run8(g_hW + 2 * 65536, h0s, g_hW + 3 * 65536, h1s, gat4, tx, nullptr, nullptr);
        lstm_epi8(gat4, g_bias + 512, c1s, h1s, h1B, c1B, g_hexp, b0, t, tx);
        __syncthreads();
    }
}

// ------------------------- persistent decoder ------------------------------
__global__ __launch_bounds__(1024, 1)
void darnn_dec(const float* __restrict__ input,
               const float* __restrict__ attndW1,
               const float* __restrict__ attndW2,
               const float* __restrict__ attndB2,
               const float* __restrict__ dWih0,
               const float* __restrict__ decinW,
               const float* __restrict__ decinB,
               const float* __restrict__ projW,
               const float* __restrict__ projB,
               float* __restrict__ out) {
    extern __shared__ float smf[];
    float* WB   = smf;              // [j<128][260] attndW1 rows (cols 0..255)
    float* h0s  = smf + 33280;
    float* c0s  = h0s + 512;
    float* h1s  = c0s + 512;
    float* c1s  = h1s + 512;
    float* h1B  = c1s + 512;
    float* c1B  = h1B + 512;
    float* gat4 = c1B + 512;        // 8192
    float* hvp2 = gat4 + 8192;      // 1024
    float* hv   = hvp2 + 1024;      // 512 [bi*128+j]
    float* lgp  = hv + 512;         // 4 x 256
    float* a_s  = lgp + 1024;       // 256
    float* pcp  = a_s + 256;        // 1024
    float* pc   = pcp + 1024;       // 512 [h*4+bi]
    float* dW0T = pc + 512;         // 512
    float* dwin = dW0T + 512;       // 132
    float* W2ds = dwin + 132;       // 128
    float* projs = W2ds + 128;      // 257
    float* wred = projs + 257;      // 32
    float* dins = wred + 32;        // 4
    const int tx = threadIdx.x;
    const int b0 = blockIdx.x * 4;
    const float b2dv = __ldg(attndB2);

    for (int i = tx; i < 128 * 256; i += 1024) {
        int j = i >> 8, h = i & 255;
        WB[j * 260 + h] = attndW1[j * 384 + h];
    }
    if (tx < 128) W2ds[tx] = attndW2[tx];
    if (tx < 129) dwin[tx] = decinW[tx];
    if (tx == 129) dwin[129] = decinB[0];
    if (tx < 256) projs[tx] = projW[tx];
    if (tx == 0) projs[256] = projB[0];
    if (tx < 512) dW0T[tx] = dWih0[tx];
    for (int i = tx; i < 3072; i += 1024) h0s[i] = 0.f;
    __syncthreads();

    for (int t = 0; t < 64; t++) {
        // A: hvec partials, h split 2-way (h1 half / c1 half)
        {
            int j = tx & 127, bi = (tx >> 7) & 3, sh = tx >> 9;
            const float4* Wr = reinterpret_cast<const float4*>(WB + j * 260 + sh * 128);
            const float4* S = reinterpret_cast<const float4*>(((sh) ? c1B : h1B) + bi * 128);
            float a = 0.f;
#pragma unroll 8
            for (int q = 0; q < 32; q++)
                a += dot4(Wr[q], S[q]);
            hvp2[sh * 512 + bi * 128 + j] = a;
        }
        __syncthreads();
        if (tx < 512) hv[tx] = hvp2[tx] + hvp2[512 + tx];
        __syncthreads();
        // B1: logit partials, j split 4-way
        {
            int tt = tx & 63, bi = (tx >> 6) & 3, jh = tx >> 8;
            const float* Hp = g_Hproj2 + (size_t)(b0 + bi) * 8192 + tt;
            float lg = 0.f;
#pragma unroll 4
            for (int jj = 0; jj < 32; jj++) {
                int j = jh * 32 + jj;
                lg = fmaf(tanh_mufu(Hp[j * 64] + hv[bi * 128 + j]), W2ds[j], lg);
            }
            lgp[jh * 256 + bi * 64 + tt] = lg;
        }
        __syncthreads();
        // B2: combine + softmax
        {
            bool act = tx < 256;
            int bi = (tx >> 6) & 3, w = tx >> 5;
            float lg = -3.0e38f;
            if (act)
                lg = lgp[tx] + lgp[256 + tx] + lgp[512 + tx] + lgp[768 + tx] + b2dv;
            float m = warp_max(lg);
            if (act && (tx & 31) == 0) wred[w] = m;
            __syncthreads();
            m = fmaxf(wred[bi * 2], wred[bi * 2 + 1]);
            float ex = act ? __expf(lg - m) : 0.f;
            float sm = warp_sum(ex);
            if (act && (tx & 31) == 0) wred[16 + w] = sm;
            __syncthreads();
            if (act)
                a_s[tx] = ex / (wred[16 + bi * 2] + wred[16 + bi * 2 + 1]);
        }
        __syncthreads();
        // C: context partials, tt split 2-way
        {
            int h = tx & 127, bi = (tx >> 7) & 3, th = tx >> 9;
            const float* hx = g_hexp + ((size_t)(b0 + bi) * 64 + th * 32) * 128 + h;
            const float* av = a_s + bi * 64 + th * 32;
            float p = 0.f;
#pragma unroll 8
            for (int tt = 0; tt < 32; tt++)
                p = fmaf(av[tt], hx[tt * 128], p);
            pcp[th * 512 + bi * 128 + h] = p;
        }
        __syncthreads();
        if (tx < 512) {
            int h = tx & 127, bi = tx >> 7;
            pc[h * 4 + bi] = pcp[tx] + pcp[512 + tx];
        }
        __syncthreads();
        // din
        {
            bool act = tx < 256;
            float r = 0.f;
            if (act) {
                int hh = tx & 63, bi = tx >> 6;
                r = pc[hh * 4 + bi] * dwin[hh] + pc[(hh + 64) * 4 + bi] * dwin[hh + 64];
            }
            r = warp_sum(r);
            if (act && (tx & 31) == 0) wred[tx >> 5] = r;
            __syncthreads();
            if (tx < 4)
                dins[tx] = wred[2 * tx] + wred[2 * tx + 1]
                         + dwin[128] * input[((size_t)(b0 + tx) * 64 + t) * 128]
                         + dwin[129];
        }
        __syncthreads();
        cell_run8(nullptr, nullptr, g_hW + 4 * 65536, h0s, gat4, tx, dW0T, dins);
        lstm_epi8(gat4, g_bias + 1024, c0s, h0s, nullptr, nullptr, nullptr, b0, t, tx);
        __syncthreads();
        cell_run8(g_hW + 5 * 65536, h0s, g_hW + 6 * 65536, h1s, gat4, tx, nullptr, nullptr);
        lstm_epi8(gat4, g_bias + 1536, c1s, h1s, h1B, c1B, nullptr, b0, t, tx);
        __syncthreads();
    }
    // output projection
    {
        bool act = tx < 256;
        float r = 0.f;
        if (act) {
            int hh = tx & 63, bi = tx >> 6;
            r = h1s[hh * 4 + bi] * projs[hh]
              + h1s[(hh + 64) * 4 + bi] * projs[hh + 64]
              + pc[hh * 4 + bi] * projs[128 + hh]
              + pc[(hh + 64) * 4 + bi] * projs[192 + hh];
        }
        r = warp_sum(r);
        if (act && (tx & 31) == 0) wred[tx >> 5] = r;
        __syncthreads();
        if (tx < 4)
            out[b0 + tx] = wred[2 * tx] + wred[2 * tx + 1] + projs[256];
    }
}

// --------------------------------- launcher ---------------------------------
extern "C" void kernel_launch(void* const* d_in, const int* in_sizes, int n_in,
                              void* d_out, int out_size) {
    const float* input    = (const float*)d_in[0];
    const float* eWih0    = (const float*)d_in[1];
    const float* eWhh0    = (const float*)d_in[2];
    const float* ebih0    = (const float*)d_in[3];
    const float* ebhh0    = (const float*)d_in[4];
    const float* eWih1    = (const float*)d_in[5];
    const float* eWhh1    = (const float*)d_in[6];
    const float* ebih1    = (const float*)d_in[7];
    const float* ebhh1    = (const float*)d_in[8];
    const float* dWih0    = (const float*)d_in[9];
    const float* dWhh0    = (const float*)d_in[10];
    const float* dbih0    = (const float*)d_in[11];
    const float* dbhh0    = (const float*)d_in[12];
    const float* dWih1    = (const float*)d_in[13];
    const float* dWhh1    = (const float*)d_in[14];
    const float* dbih1    = (const float*)d_in[15];
    const float* dbhh1    = (const float*)d_in[16];
    const float* attnW1   = (const float*)d_in[17];
    const float* attnB1   = (const float*)d_in[18];
    const float* attnW2   = (const float*)d_in[19];
    const float* attnB2   = (const float*)d_in[20];
    const float* attndW1  = (const float*)d_in[21];
    const float* attndB1  = (const float*)d_in[22];
    const float* attndW2  = (const float*)d_in[23];
    const float* attndB2  = (const float*)d_in[24];
    const float* decinW   = (const float*)d_in[25];
    const float* decinB   = (const float*)d_in[26];
    const float* projW    = (const float*)d_in[27];
    const float* projB    = (const float*)d_in[28];
    (void)in_sizes; (void)n_in; (void)out_size;

    float *P, *P2, *hexp, *Hproj2, *W1Te, *W1Td;
    cudaGetSymbolAddress((void**)&P,      g_P);
    cudaGetSymbolAddress((void**)&P2,     g_P2);
    cudaGetSymbolAddress((void**)&hexp,   g_hexp);
    cudaGetSymbolAddress((void**)&Hproj2, g_Hproj2);
    cudaGetSymbolAddress((void**)&W1Te,   g_W1Te);
    cudaGetSymbolAddress((void**)&W1Td,   g_W1Td);

    static bool attrDone = false;
    if (!attrDone) {
        cudaFuncSetAttribute(darnn_enc, cudaFuncAttributeMaxDynamicSharedMemorySize, 140 * 1024);
        cudaFuncSetAttribute(darnn_dec, cudaFuncAttributeMaxDynamicSharedMemorySize, 204 * 1024);
        attrDone = true;
    }

    darnn_prep<<<518, 1024>>>(eWih0, eWhh0, eWih1, eWhh1, dWhh0, dWih1, dWhh1,
                              ebih0, ebhh0, ebih1, ebhh1, dbih0, dbhh0, dbih1, dbhh1,
                              attnW1, attndW1);
    darnn_penc<<<(B_ * E_) / 4, 256>>>(input, W1Te, attnB1, P);
    darnn_ptrans<<<B_ * 2, 256>>>(P, P2);
    darnn_enc<<<128, 1024, 140 * 1024>>>(input, attnW1, attnW2, attnB2);
    darnn_hproj<<<(B_ * T_) / 16, 256>>>(hexp, W1Td, attndB1, Hproj2);
    darnn_dec<<<128, 1024, 204 * 1024>>>(input, attndW1, attndW2, attndB2,
                                         dWih0, decinW, decinB, projW, projB,
                                         (float*)d_out);
}